// round 15
// baseline (speedup 1.0000x reference)
#include <cuda_runtime.h>
#include <cuda_bf16.h>
#include <math.h>
#include <stdint.h>

#define E_ 4
#define B_ 8
#define NP_ 96
#define H_ 1024
#define OUT_ 4096
#define NQ_ 144
#define FFH_ 4096
#define MAXT 40

__device__ __constant__ int c_SQ[3] = {64, 48, 32};
__device__ __constant__ int c_L[3]  = {320, 304, 288};
__device__ __constant__ int c_QO[3] = {0, 64, 112};
__device__ __constant__ int c_IO[3] = {0, 256, 512};

// ---------------- scratch ----------------------------------------------------
__device__ float g_gates[B_ * E_];
__device__ float g_x  [NP_ * 64L * H_];
__device__ float g_q  [NP_ * 64L * H_];
__device__ float g_k  [NP_ * 320L * H_];
__device__ float g_v  [NP_ * 320L * H_];
__device__ float g_kv0[NP_ * 320L * H_];
__device__ float g_comb[B_ * (long)NQ_ * OUT_];

// bf16 hi/lo activation buffers
__device__ __nv_bfloat16 g_xnh[NP_ * 64L * H_],  g_xnl[NP_ * 64L * H_];
__device__ __nv_bfloat16 g_kvnh[NP_ * 320L * H_], g_kvnl[NP_ * 320L * H_];
__device__ __nv_bfloat16 g_hh [NP_ * 64L * FFH_], g_hl [NP_ * 64L * FFH_];

// split-bf16 weights (hi/lo)
#define OFF_ATTNIN  0L
#define OFF_ATTNOUT 25165824L
#define OFF_FC      33554432L
#define OFF_PROJ    67108864L
#define OFF_OUTP    100663296L
#define W_TOTAL     117440512L

__device__ __nv_bfloat16 g_wh[W_TOTAL];
__device__ __nv_bfloat16 g_wl[W_TOTAL];

__device__ __forceinline__ float* bufptr(int id) {
    switch (id) {
        case 0: return g_x;  case 2: return g_kv0;
        case 4: return g_q;  case 5: return g_k;
        default: return g_v;
    }
}
__device__ __forceinline__ long bufstride(int id) {
    switch (id) {
        case 0: case 1: case 4: return 64L * H_;
        case 7: return 64L * FFH_;
        default: return 320L * H_;
    }
}
__device__ __forceinline__ __nv_bfloat16* bp16h(int id) {
    switch (id) { case 1: return g_xnh; case 3: return g_kvnh; default: return g_hh; }
}
__device__ __forceinline__ __nv_bfloat16* bp16l(int id) {
    switch (id) { case 1: return g_xnl; case 3: return g_kvnl; default: return g_hl; }
}

// ---------------- inline packed-tile scheduling ------------------------------
__device__ __forceinline__ int tile_row(int zi, int j, int* e_out) {
    int base = 0;
    for (int e = 0; e < 4; e++) {
        int nb = 0;
        #pragma unroll
        for (int b = 0; b < 8; b++) nb += (g_gates[b * 4 + e] != 0.f);
        int rows_e = nb * 144;
        int tiles_e = (rows_e + 63) >> 6;
        if (zi < base + tiles_e) {
            *e_out = e;
            int lrow = (zi - base) * 64 + j;
            if (lrow >= rows_e) return -1;
            int bi = lrow / 144, rr = lrow % 144;
            int b = 0, cnt = 0;
            for (; b < 8; b++) {
                if (g_gates[b * 4 + e] != 0.f) { if (cnt == bi) break; cnt++; }
            }
            int s, r0;
            if (rr < 64)       { s = 0; r0 = rr; }
            else if (rr < 112) { s = 1; r0 = rr - 64; }
            else               { s = 2; r0 = rr - 112; }
            return (e * 24 + b * 3 + s) * 64 + r0;
        }
        base += tiles_e;
    }
    return -2;
}

// ---------------- weight splitting (single launch) ---------------------------
__global__ void split_all(const float* __restrict__ w_attnin,
                          const float* __restrict__ w_attnout,
                          const float* __restrict__ w_fc,
                          const float* __restrict__ w_proj,
                          const float* __restrict__ w_outp) {
    long i = (long)blockIdx.x * blockDim.x + threadIdx.x;
    long stride = (long)gridDim.x * blockDim.x;
    for (; i < W_TOTAL; i += stride) {
        const float* src; long rel;
        if (i < OFF_ATTNOUT)      { src = w_attnin;  rel = i; }
        else if (i < OFF_FC)      { src = w_attnout; rel = i - OFF_ATTNOUT; }
        else if (i < OFF_PROJ)    { src = w_fc;      rel = i - OFF_FC; }
        else if (i < OFF_OUTP)    { src = w_proj;    rel = i - OFF_PROJ; }
        else                      { src = w_outp;    rel = i - OFF_OUTP; }
        float x = src[rel];
        __nv_bfloat16 h = __float2bfloat16(x);
        g_wh[i] = h;
        g_wl[i] = __float2bfloat16(x - __bfloat162float(h));
    }
}

// ---------------- block reductions -------------------------------------------
__device__ __forceinline__ float blockReduceSum(float v, float* sbuf) {
    int t = threadIdx.x;
    for (int o = 16; o; o >>= 1) v += __shfl_down_sync(0xffffffffu, v, o);
    if ((t & 31) == 0) sbuf[t >> 5] = v;
    __syncthreads();
    if (t < 8) {
        v = sbuf[t];
        for (int o = 4; o; o >>= 1) v += __shfl_down_sync(0xffu, v, o);
        if (t == 0) sbuf[0] = v;
    }
    __syncthreads();
    float r = sbuf[0];
    __syncthreads();
    return r;
}
__device__ __forceinline__ float blockReduceMax(float v, float* sbuf) {
    int t = threadIdx.x;
    for (int o = 16; o; o >>= 1) v = fmaxf(v, __shfl_down_sync(0xffffffffu, v, o));
    if ((t & 31) == 0) sbuf[t >> 5] = v;
    __syncthreads();
    if (t < 8) {
        v = sbuf[t];
        for (int o = 4; o; o >>= 1) v = fmaxf(v, __shfl_down_sync(0xffu, v, o));
        if (t == 0) sbuf[0] = v;
    }
    __syncthreads();
    float r = sbuf[0];
    __syncthreads();
    return r;
}

// ---------------- gating -----------------------------------------------------
__global__ void gate_kernel(const float* __restrict__ img,
                            const int* __restrict__ task_ids,
                            const int* __restrict__ elem_ids,
                            const float* __restrict__ task_emb,
                            const float* __restrict__ elem_emb,
                            const float* __restrict__ glw,
                            const float* __restrict__ glb,
                            const float* __restrict__ gw,
                            const float* __restrict__ gb) {
    int b = blockIdx.x;
    int t = threadIdx.x;
    __shared__ float gi[1536];
    __shared__ float sn[1536];
    __shared__ float red[32];
    __shared__ float lg[4];

    float acc0 = 0.f, acc1 = 0.f, acc2 = 0.f, acc3 = 0.f;
    const float* ib = img + (long)b * 576 * H_;
    for (int r = 0; r < 576; r++) {
        const float* row = ib + (long)r * H_;
        acc0 += row[t];        acc1 += row[t + 256];
        acc2 += row[t + 512];  acc3 += row[t + 768];
    }
    const float inv576 = 1.f / 576.f;
    gi[t]       = acc0 * inv576;  gi[t + 256] = acc1 * inv576;
    gi[t + 512] = acc2 * inv576;  gi[t + 768] = acc3 * inv576;
    gi[1024 + t] = task_emb[task_ids[b] * 256 + t];
    gi[1280 + t] = elem_emb[elem_ids[b] * 256 + t];
    __syncthreads();

    float s1 = 0.f;
    for (int d = t; d < 1536; d += 256) s1 += gi[d];
    s1 = blockReduceSum(s1, red);
    float m = s1 / 1536.f;
    float s2 = 0.f;
    for (int d = t; d < 1536; d += 256) { float dd = gi[d] - m; s2 += dd * dd; }
    s2 = blockReduceSum(s2, red);
    float rs = rsqrtf(s2 / 1536.f + 1e-5f);
    for (int d = t; d < 1536; d += 256) sn[d] = (gi[d] - m) * rs * glw[d] + glb[d];
    __syncthreads();

    for (int e = 0; e < 4; e++) {
        float pd = 0.f;
        for (int d = t; d < 1536; d += 256) pd += sn[d] * gw[e * 1536 + d];
        pd = blockReduceSum(pd, red);
        if (t == 0) {
            float l = pd + gb[e];
            lg[e] = fminf(fmaxf(l, -15.f), 15.f);
        }
        __syncthreads();
    }
    if (t == 0) {
        float mx = fmaxf(fmaxf(lg[0], lg[1]), fmaxf(lg[2], lg[3]));
        float pe[4]; float den = 0.f;
        for (int e = 0; e < 4; e++) { pe[e] = expf(lg[e] - mx); den += pe[e]; }
        for (int e = 0; e < 4; e++) pe[e] /= den;
        int i1 = 0;
        for (int e = 1; e < 4; e++) if (pe[e] > pe[i1]) i1 = e;
        int i2 = -1;
        for (int e = 0; e < 4; e++) {
            if (e == i1) continue;
            if (i2 < 0 || pe[e] > pe[i2]) i2 = e;
        }
        float sum2 = pe[i1] + pe[i2] + 1e-9f;
        for (int e = 0; e < 4; e++) g_gates[b * 4 + e] = 0.f;
        g_gates[b * 4 + i1] = pe[i1] / sum2;
        g_gates[b * 4 + i2] = pe[i2] / sum2;
    }
}

// ---------------- fused prep: build kv0/x + layer-0 LN (kv + x) --------------
__global__ void prep_kernel(const float* __restrict__ query,
                            const float* __restrict__ img,
                            const float* __restrict__ pp,
                            const float* __restrict__ ln1_w,
                            const float* __restrict__ ln1_b,
                            const float* __restrict__ ln1kv_w,
                            const float* __restrict__ ln1kv_b) {
    int p = blockIdx.y;
    int e = p / 24, r = p % 24, b = r / 3, s = r % 3;
    if (g_gates[b * 4 + e] == 0.f) return;
    int tk = blockIdx.x;
    int L = c_L[s];
    if (tk >= L) return;
    int sq = c_SQ[s];
    const float* src;
    if (tk < sq) {
        src = query + ((long)e * NQ_ + c_QO[s] + tk) * H_;
    } else {
        int j = c_IO[s] + tk - sq;
        src = (j < 576) ? img + ((long)b * 576 + j) * H_
                        : pp  + ((long)b * 192 + (j - 576)) * H_;
    }
    __shared__ float sx[1024];
    __shared__ float red[32];
    int t = threadIdx.x;
    float s1 = 0.f;
    #pragma unroll
    for (int j = 0; j < 4; j++) { float v = src[t + j * 256]; sx[t + j * 256] = v; s1 += v; }

    float* dst = g_kv0 + (long)p * 320 * H_ + (long)tk * H_;
    #pragma unroll
    for (int j = 0; j < 4; j++) dst[t + j * 256] = sx[t + j * 256];
    if (tk < sq) {
        float* xd = g_x + (long)p * 64 * H_ + (long)tk * H_;
        #pragma unroll
        for (int j = 0; j < 4; j++) xd[t + j * 256] = sx[t + j * 256];
    }

    s1 = blockReduceSum(s1, red);
    float m = s1 / 1024.f;
    float s2 = 0.f;
    #pragma unroll
    for (int j = 0; j < 4; j++) { float d = sx[t + j * 256] - m; s2 += d * d; }
    s2 = blockReduceSum(s2, red);
    float rs = rsqrtf(s2 / 1024.f + 1e-5f);

    const float* wkv = ln1kv_w + (long)(e * 2) * H_;
    const float* bkv = ln1kv_b + (long)(e * 2) * H_;
    long koff = (long)p * 320 * H_ + (long)tk * H_;
    #pragma unroll
    for (int j = 0; j < 4; j++) {
        int d = t + j * 256;
        float val = (sx[d] - m) * rs * wkv[d] + bkv[d];
        __nv_bfloat16 h = __float2bfloat16(val);
        g_kvnh[koff + d] = h;
        g_kvnl[koff + d] = __float2bfloat16(val - __bfloat162float(h));
    }
    if (tk < sq) {
        const float* wq = ln1_w + (long)(e * 2) * H_;
        const float* bq = ln1_b + (long)(e * 2) * H_;
        long xoff = (long)p * 64 * H_ + (long)tk * H_;
        #pragma unroll
        for (int j = 0; j < 4; j++) {
            int d = t + j * 256;
            float val = (sx[d] - m) * rs * wq[d] + bq[d];
            __nv_bfloat16 h = __float2bfloat16(val);
            g_xnh[xoff + d] = h;
            g_xnl[xoff + d] = __float2bfloat16(val - __bfloat162float(h));
        }
    }
}

// ---------------- row LayerNorm → bf16 hi/lo ---------------------------------
__global__ void ln_rows(int src, int dst,
                        const float* __restrict__ wbase,
                        const float* __restrict__ bbase,
                        int m_is_L, int layer) {
    int p = blockIdx.y;
    int e = p / 24, r = p % 24, b = r / 3, s = r % 3;
    if (g_gates[b * 4 + e] == 0.f) return;
    int M = m_is_L ? c_L[s] : c_SQ[s];
    int row = blockIdx.x;
    if (row >= M) return;
    const float* x = bufptr(src) + (long)p * bufstride(src) + (long)row * H_;
    long doff = (long)p * bufstride(dst) + (long)row * H_;
    __nv_bfloat16* yh = bp16h(dst) + doff;
    __nv_bfloat16* yl = bp16l(dst) + doff;
    const float* w  = wbase + (long)(e * 2 + layer) * H_;
    const float* bb = bbase + (long)(e * 2 + layer) * H_;
    __shared__ float sx[1024];
    __shared__ float red[32];
    int t = threadIdx.x;
    float s1 = 0.f;
    #pragma unroll
    for (int j = 0; j < 4; j++) { float v = x[t + j * 256]; sx[t + j * 256] = v; s1 += v; }
    s1 = blockReduceSum(s1, red);
    float m = s1 / 1024.f;
    float s2 = 0.f;
    #pragma unroll
    for (int j = 0; j < 4; j++) { float d = sx[t + j * 256] - m; s2 += d * d; }
    s2 = blockReduceSum(s2, red);
    float rs = rsqrtf(s2 / 1024.f + 1e-5f);
    #pragma unroll
    for (int j = 0; j < 4; j++) {
        int d = t + j * 256;
        float val = (sx[d] - m) * rs * w[d] + bb[d];
        __nv_bfloat16 h = __float2bfloat16(val);
        yh[d] = h;
        yl[d] = __float2bfloat16(val - __bfloat162float(h));
    }
}

// ---------------- tensor-core GEMM v3: BN=256, warp 32x64, cp.async ----------
#define SPITCH 40
#define GA_BYTES 5120                       // one A tile (hi or lo): 64*40*2
#define GW_BYTES 20480                      // one W tile (hi or lo): 256*40*2
#define GSTG (2 * GA_BYTES + 2 * GW_BYTES)  // 51200 per stage
#define GTSM (2 * GSTG)                     // 102400
// out_gemm legacy buffers
#define OSTG 30720
#define OTSM (2 * OSTG)

struct GArgs {
    int a_id; int c_id;
    long wh_off; long w_stride;
    const float* bias; long bias_stride;
    const float* ls;
    int N; int K;
    int m_is_L;
    int epi;     // 0 fp32 store, 1 gelu->bf16hi/lo, 2 C += ls*(c+bias), 4 kv-split
    int layer;
    int packed;
};

__device__ __forceinline__ void mma_bf16(float* d, const uint32_t* a, const uint32_t* b) {
    asm volatile(
        "mma.sync.aligned.m16n8k16.row.col.f32.bf16.bf16.f32 "
        "{%0,%1,%2,%3}, {%4,%5,%6,%7}, {%8,%9}, {%0,%1,%2,%3};\n"
        : "+f"(d[0]), "+f"(d[1]), "+f"(d[2]), "+f"(d[3])
        : "r"(a[0]), "r"(a[1]), "r"(a[2]), "r"(a[3]), "r"(b[0]), "r"(b[1]));
}
__device__ __forceinline__ void ldsm4(uint32_t& r0, uint32_t& r1, uint32_t& r2, uint32_t& r3,
                                      uint32_t addr) {
    asm volatile("ldmatrix.sync.aligned.m8n8.x4.shared.b16 {%0,%1,%2,%3}, [%4];"
                 : "=r"(r0), "=r"(r1), "=r"(r2), "=r"(r3) : "r"(addr));
}
__device__ __forceinline__ void split8(float4 f0, float4 f1, uint4& hi, uint4& lo) {
    __nv_bfloat162 h0 = __floats2bfloat162_rn(f0.x, f0.y);
    __nv_bfloat162 h1 = __floats2bfloat162_rn(f0.z, f0.w);
    __nv_bfloat162 h2 = __floats2bfloat162_rn(f1.x, f1.y);
    __nv_bfloat162 h3 = __floats2bfloat162_rn(f1.z, f1.w);
    float2 a0 = __bfloat1622float2(h0), a1 = __bfloat1622float2(h1);
    float2 a2 = __bfloat1622float2(h2), a3 = __bfloat1622float2(h3);
    __nv_bfloat162 l0 = __floats2bfloat162_rn(f0.x - a0.x, f0.y - a0.y);
    __nv_bfloat162 l1 = __floats2bfloat162_rn(f0.z - a1.x, f0.w - a1.y);
    __nv_bfloat162 l2 = __floats2bfloat162_rn(f1.x - a2.x, f1.y - a2.y);
    __nv_bfloat162 l3 = __floats2bfloat162_rn(f1.z - a3.x, f1.w - a3.y);
    hi.x = *(uint32_t*)&h0; hi.y = *(uint32_t*)&h1; hi.z = *(uint32_t*)&h2; hi.w = *(uint32_t*)&h3;
    lo.x = *(uint32_t*)&l0; lo.y = *(uint32_t*)&l1; lo.z = *(uint32_t*)&l2; lo.w = *(uint32_t*)&l3;
}

__device__ __forceinline__ void cpa16(uint32_t dst, const void* src) {
    asm volatile("cp.async.cg.shared.global [%0], [%1], 16;" :: "r"(dst), "l"(src));
}
__device__ __forceinline__ void cpa16z(uint32_t dst) {
    asm volatile("cp.async.cg.shared.global [%0], [%1], 16, 0;"
                 :: "r"(dst), "l"((const void*)g_wh));
}
#define CP_COMMIT asm volatile("cp.async.commit_group;" ::: "memory")
#define CP_WAIT1  asm volatile("cp.async.wait_group 1;" ::: "memory")
#define CP_WAIT0  asm volatile("cp.async.wait_group 0;" ::: "memory")

__global__ void __launch_bounds__(256) gemm_k(GArgs g) {
    int zi = blockIdx.z;
    int e = 0, p = 0, M = 64, m0 = 0;
    long pbaseA = 0;

    if (g.packed) {
        int probe = tile_row(zi, 0, &e);
        if (probe == -2) return;
    } else {
        p = zi;
        e = p / 24;
        int r = p % 24, b = r / 3, s = r % 3;
        if (g_gates[b * 4 + e] == 0.f) return;
        M = g.m_is_L ? c_L[s] : c_SQ[s];
        m0 = blockIdx.x * 64;
        if (m0 >= M) return;
        pbaseA = (long)p * bufstride(g.a_id);
    }
    int n0 = blockIdx.y * 256;

    const __nv_bfloat16* Wh = g_wh + g.wh_off + (long)(e * 2 + g.layer) * g.w_stride;
    const __nv_bfloat16* Wl = g_wl + g.wh_off + (long)(e * 2 + g.layer) * g.w_stride;
    const float* bias = g.bias + (long)(e * 2 + g.layer) * g.bias_stride;

    extern __shared__ char dsm[];
    uint32_t smem_u = (uint32_t)__cvta_generic_to_shared(dsm);

    int tid = threadIdx.x;
    // A loader: row = tid>>2 (64 rows), 16B chunk = tid&3
    int arow = tid >> 2, akq = (tid & 3) << 3;
    const __nv_bfloat16* ahrow = nullptr;
    const __nv_bfloat16* alrow = nullptr;
    if (g.packed) {
        int e2;
        int rm = tile_row(zi, arow, &e2);
        if (rm >= 0) {
            long aoff = (long)rm * g.K + akq;
            ahrow = bp16h(g.a_id) + aoff;
            alrow = bp16l(g.a_id) + aoff;
        }
    } else if (m0 + arow < M) {
        long aoff = pbaseA + (long)(m0 + arow) * g.K + akq;
        ahrow = bp16h(g.a_id) + aoff;
        alrow = bp16l(g.a_id) + aoff;
    }
    // W loader: rows wr0 + 64*j (j=0..3), chunk tid&3
    int wr0 = tid >> 2, wkq = (tid & 3) << 3;
    const __nv_bfloat16* whp = Wh + (long)(n0 + wr0) * g.K + wkq;
    const __nv_bfloat16* wlp = Wl + (long)(n0 + wr0) * g.K + wkq;
    long wjump = 64L * g.K;

    uint32_t sA_off = (uint32_t)(arow * SPITCH + akq) * 2;
    uint32_t sW_off = (uint32_t)(wr0 * SPITCH + wkq) * 2;

    // compute mapping: 8 warps (2 x 4), warp tile 32x64
    int lane = tid & 31, w = tid >> 5;
    int gq_ = lane >> 2, qq = lane & 3;
    int wm = w & 1, wn = w >> 1;
    int abase = wm * 32, wbase = wn * 64;

    int lr = lane & 7, tq = lane >> 3;
    int a_r = abase + ((tq & 1) << 3) + lr;
    int a_k = (tq >> 1) << 3;
    int b_r = wbase + ((tq >> 1) << 3) + lr;
    int b_k = (tq & 1) << 3;

    float acc[2][8][4];
    #pragma unroll
    for (int i = 0; i < 2; i++)
        #pragma unroll
        for (int j = 0; j < 8; j++)
            #pragma unroll
            for (int k = 0; k < 4; k++) acc[i][j][k] = 0.f;

    int nc = g.K >> 5;

    auto prefetch = [&](int c, int st) {
        uint32_t sb = smem_u + st * GSTG;
        long ko = (long)c << 5;
        if (ahrow) {
            cpa16(sb + sA_off, ahrow + ko);
            cpa16(sb + GA_BYTES + sA_off, alrow + ko);
        } else {
            cpa16z(sb + sA_off);
            cpa16z(sb + GA_BYTES + sA_off);
        }
        uint32_t wb = sb + 2 * GA_BYTES + sW_off;
        #pragma unroll
        for (int j = 0; j < 4; j++) {
            uint32_t wo = wb + j * (64 * SPITCH * 2);
            cpa16(wo, whp + ko + j * wjump);
            cpa16(wo + GW_BYTES, wlp + ko + j * wjump);
        }
        CP_COMMIT;
    };

    prefetch(0, 0);
    if (nc > 1) prefetch(1, 1);

    for (int c = 0; c < nc; c++) {
        int st = c & 1;
        if (c == nc - 1) { CP_WAIT0; } else { CP_WAIT1; }
        __syncthreads();

        uint32_t aH = smem_u + st * GSTG;
        uint32_t aL = aH + GA_BYTES;
        uint32_t wH = aH + 2 * GA_BYTES;
        uint32_t wL = wH + GW_BYTES;

        #pragma unroll
        for (int ks = 0; ks < 32; ks += 16) {
            uint32_t Ah[2][4], Al[2][4];
            #pragma unroll
            for (int mf = 0; mf < 2; mf++) {
                uint32_t off = ((a_r + mf * 16) * SPITCH + a_k + ks) * 2;
                ldsm4(Ah[mf][0], Ah[mf][1], Ah[mf][2], Ah[mf][3], aH + off);
                ldsm4(Al[mf][0], Al[mf][1], Al[mf][2], Al[mf][3], aL + off);
            }
            #pragma unroll
            for (int nfp = 0; nfp < 4; nfp++) {
                uint32_t Bh[2][2], Bl[2][2];
                uint32_t off = ((b_r + nfp * 16) * SPITCH + b_k + ks) * 2;
                ldsm4(Bh[0][0], Bh[0][1], Bh[1][0], Bh[1][1], wH + off);
                ldsm4(Bl[0][0], Bl[0][1], Bl[1][0], Bl[1][1], wL + off);
                #pragma unroll
                for (int mf = 0; mf < 2; mf++)
                    #pragma unroll
                    for (int d = 0; d < 2; d++) {
                        int nf = nfp * 2 + d;
                        mma_bf16(acc[mf][nf], Ah[mf], Bh[d]);
                        mma_bf16(acc[mf][nf], Ah[mf], Bl[d]);
                        mma_bf16(acc[mf][nf], Al[mf], Bh[d]);
                    }
            }
        }
        __syncthreads();
        if (c + 2 < nc) prefetch(c + 2, st);
    }

    // epilogue
    float* C = bufptr(g.c_id);
    __nv_bfloat16* Ch = bp16h(g.c_id);
    __nv_bfloat16* Cl = bp16l(g.c_id);
    long pbaseC = g.packed ? 0 : (long)p * bufstride(g.c_id);
    long pbaseKV = (long)p * 320L * H_;
    const float* lsp = (g.epi == 2) ? (g.ls + (long)(e * 2 + g.layer) * H_) : nullptr;

    #pragma unroll
    for (int mf = 0; mf < 2; mf++) {
        #pragma unroll
        for (int half = 0; half < 2; half++) {
            int ml = abase + mf * 16 + gq_ + half * 8;
            long rowoff;
            if (g.packed) {
                int e2;
                int rm = tile_row(zi, ml, &e2);
                if (rm < 0) continue;
                rowoff = (long)rm * g.N;
            } else {
                int m = m0 + ml;
                if (m >= M) continue;
                rowoff = pbaseC + (long)m * g.N;
                if (g.epi == 4) rowoff = pbaseKV + (long)m * (long)H_;
            }
            #pragma unroll
            for (int nf = 0; nf < 8; nf++) {
                int n = n0 + wbase + nf * 8 + qq * 2;
                float v0 = acc[mf][nf][half * 2 + 0] + bias[n];
                float v1 = acc[mf][nf][half * 2 + 1] + bias[n + 1];
                if (g.epi == 0) {
                    long idx = rowoff + n;
                    C[idx] = v0; C[idx + 1] = v1;
                } else if (g.epi == 1) {
                    long idx = rowoff + n;
                    float t0 = v0 * 0.5f * (1.f + erff(v0 * 0.70710678118654752f));
                    float t1 = v1 * 0.5f * (1.f + erff(v1 * 0.70710678118654752f));
                    __nv_bfloat16 h0 = __float2bfloat16(t0);
                    __nv_bfloat16 h1 = __float2bfloat16(t1);
                    Ch[idx] = h0;     Ch[idx + 1] = h1;
                    Cl[idx]     = __float2bfloat16(t0 - __bfloat162float(h0));
                    Cl[idx + 1] = __float2bfloat16(t1 - __bfloat162float(h1));
                } else if (g.epi == 2) {
                    long idx = rowoff + n;
                    C[idx]     += lsp[n] * v0;
                    C[idx + 1] += lsp[n + 1] * v1;
                } else {
                    float* dst = (n < 1024) ? g_k : g_v;
                    long idx = rowoff + (n & 1023);
                    dst[idx] = v0; dst[idx + 1] = v1;
                }
            }
        }
    }
}

// ---------------- attention: 4 q-rows per block ------------------------------
__global__ void attn_kernel() {
    int p = blockIdx.z;
    int e = p / 24, r = p % 24, b = r / 3, s = r % 3;
    if (g_gates[b * 4 + e] == 0.f) return;
    int sq = c_SQ[s];
    int r0 = blockIdx.x * 4;
    if (r0 >= sq) return;
    int L = c_L[s];
    int h = blockIdx.y;
    int t = threadIdx.x;

    __shared__ float sc[4][320];
    __shared__ float qv[4][64];
    __shared__ float red[32];
    __shared__ float cbuf[4][4][64];
    __shared__ float inv[4];

    const float* Qb = g_q + (long)p * 64 * H_ + (long)r0 * H_ + h * 64;
    const float* K  = g_k + (long)p * 320 * H_ + h * 64;
    const float* V  = g_v + (long)p * 320 * H_ + h * 64;

    qv[t >> 6][t & 63] = Qb[(long)(t >> 6) * H_ + (t & 63)];
    __syncthreads();

    for (int k = t; k < L; k += 256) {
        const float* kr = K + (long)k * H_;
        float d0 = 0.f, d1 = 0.f, d2 = 0.f, d3 = 0.f;
        #pragma unroll
        for (int dd = 0; dd < 64; dd++) {
            float kvv = kr[dd];
            d0 += qv[0][dd] * kvv;
            d1 += qv[1][dd] * kvv;
            d2 += qv[2][dd] * kvv;
            d3 += qv[3][dd] * kvv;
        }
        sc[0][k] = d0 * 0.125f;
        sc[1][k] = d1 * 0.125f;
        sc[2][k] = d2 * 0.125f;
        sc[3][k] = d3 * 0.125f;
    }
    __syncthreads();

    for (int rr = 0; rr < 4; rr++) {
        float mx = -1e30f;
        for (int k = t; k < L; k += 256) mx = fmaxf(mx, sc[rr][k]);
        mx = blockReduceMax(mx, red);
        float sum = 0.f;
        for (int k = t; k < L; k += 256) {
            float ev = expf(sc[rr][k] - mx);
            sc[rr][k] = ev;
            sum += ev;
        }
        sum = blockReduceSum(sum, red);
        if (t == 0) inv[rr] = 1.f / sum;
        __syncthreads();
    }

    int d = t & 63, ch = t >> 6;
    float a0 = 0.f, a1 = 0.f, a2 = 0.f, a3 = 0.f;
    for (int k = ch; k < L; k += 4) {
        float vv = V[(long)k * H_ + d];
        a0 += sc[0][k] * vv;
        a1 += sc[1][k] * vv;
        a2 += sc[2][k] * vv;
        a3 += sc[3][k] * vv;
    }
    cbuf[ch][0][d] = a0;
    cbuf[ch][1][d] = a1;
    cbuf[ch][2][d] = a2;
    cbuf[ch][3][d] = a3;
    __syncthreads();

    {
        int rr = t >> 6, dd = t & 63;
        float o = (cbuf[0][rr][dd] + cbuf[1][rr][dd] + cbuf[2][rr][dd] + cbuf[3][rr][dd]) * inv[rr];
        long ooff = (long)p * 64 * H_ + (long)(r0 + rr) * H_ + h * 64 + dd;
        __nv_bfloat16 oh = __float2bfloat16(o);
        g_xnh[ooff] = oh;
        g_xnl[ooff] = __float2bfloat16(o - __bfloat162float(oh));
    }
}

// ---------------- expert-weighted output projection (legacy path) ------------
__global__ void __launch_bounds__(256) out_gemm(const float* __restrict__ outp_b) {
    int b = blockIdx.z;
    int m0 = blockIdx.x * 64;
    int n0 = blockIdx.y * 128;

    extern __shared__ char dsm[];
    uint32_t smem_u = (uint32_t)__cvta_generic_to_shared(dsm);

    int tid = threadIdx.x;
    int arow = tid >> 2, akq = (tid & 3) << 3;
    int wrow = tid >> 1, wkq = (tid & 1) << 4;
    int lane = tid & 31, w = tid >> 5;
    int gq_ = lane >> 2, qq = lane & 3;
    int wm = w & 1, wn = w >> 1;
    int abase = wm * 32, wbase = wn * 32;

    int lr = lane & 7, tq = lane >> 3;
    int a_r = abase + ((tq & 1) << 3) + lr;
    int a_k = (tq >> 1) << 3;
    int b_r = wbase + ((tq >> 1) << 3) + lr;
    int b_k = (tq & 1) << 3;

    int qg = m0 + arow;
    bool aval = qg < NQ_;
    int s = 0, lrq = 0;
    if (aval) {
        s = (qg < 64) ? 0 : ((qg < 112) ? 1 : 2);
        lrq = qg - c_QO[s];
    }

    float tot[2][4][4];
    #pragma unroll
    for (int i = 0; i < 2; i++)
        #pragma unroll
        for (int j = 0; j < 4; j++)
            #pragma unroll
            for (int k = 0; k < 4; k++) tot[i][j][k] = 0.f;

    for (int e = 0; e < 4; e++) {
        float gt = g_gates[b * 4 + e];
        if (gt == 0.f) continue;
        const float* aptr = g_x + ((long)(e * 24 + b * 3 + s) * 64 + lrq) * H_ + akq;
        long wb = OFF_OUTP + (long)e * OUT_ * H_ + (long)(n0 + wrow) * H_ + wkq;
        const __nv_bfloat16* whp = g_wh + wb;
        const __nv_bfloat16* wlp = g_wl + wb;

        float acc[2][4][4];
        #pragma unroll
        for (int i = 0; i < 2; i++)
            #pragma unroll
            for (int j = 0; j < 4; j++)
                #pragma unroll
                for (int k = 0; k < 4; k++) acc[i][j][k] = 0.f;

        float4 f0, f1;
        uint4 rah, ral, vh0, vh1, vl0, vl1;
        uint4 zz = make_uint4(0u, 0u, 0u, 0u);

        f0 = f1 = make_float4(0.f, 0.f, 0.f, 0.f);
        if (aval) { f0 = *(const float4*)(aptr); f1 = *(const float4*)(aptr + 4); }
        split8(f0, f1, rah, ral);
        if (!aval) { rah = zz; ral = zz; }
        vh0 = *(const uint4*)(whp);  vh1 = *(const uint4*)(whp + 8);
        vl0 = *(const uint4*)(wlp);  vl1 = *(const uint4*)(wlp + 8);

        __syncthreads();
        {
            __nv_bfloat16* sAh = (__nv_bfloat16*)(dsm);
            __nv_bfloat16* sAl = (__nv_bfloat16*)(dsm + 5120);
            __nv_bfloat16* sWh = (__nv_bfloat16*)(dsm + 10240);
            __nv_bfloat16* sWl = (__nv_bfloat16*)(dsm + 20480);
            *(uint4*)&sAh[arow * SPITCH + akq] = rah;
            *(uint4*)&sAl[arow * SPITCH + akq] = ral;
            *(uint4*)&sWh[wrow * SPITCH + wkq]     = vh0;
            *(uint4*)&sWh[wrow * SPITCH + wkq + 8] = vh1;
            *(uint4*)&sWl[wrow * SPITCH + wkq]     = vl0;
            *(uint4*)&sWl[wrow * SPITCH + wkq + 8] = vl1;
        }
        __syncthreads();

        const int nc = H_ >> 5;
        for (int c = 0; c < nc; c++) {
            int st = c & 1;
            bool nx = (c + 1 < nc);
            if (nx) {
                long off = (long)(c + 1) << 5;
                f0 = f1 = make_float4(0.f, 0.f, 0.f, 0.f);
                if (aval) { f0 = *(const float4*)(aptr + off); f1 = *(const float4*)(aptr + off + 4); }
                split8(f0, f1, rah, ral);
                if (!aval) { rah = zz; ral = zz; }
                vh0 = *(const uint4*)(whp + off);  vh1 = *(const uint4*)(whp + off + 8);
                vl0 = *(const uint4*)(wlp + off);  vl1 = *(const uint4*)(wlp + off + 8);
            }

            uint32_t aH = smem_u + st * OSTG;
            uint32_t aL = aH + 5120;
            uint32_t wH = aH + 10240;
            uint32_t wL = aH + 20480;

            #pragma unroll
            for (int ks = 0; ks < 32; ks += 16) {
                uint32_t Ah[2][4], Al[2][4], Bh[4][2], Bl[4][2];
                #pragma unroll
                for (int mf = 0; mf < 2; mf++) {
                    uint32_t off = ((a_r + mf * 16) * SPITCH + a_k + ks) * 2;
                    ldsm4(Ah[mf][0], Ah[mf][1], Ah[mf][2], Ah[mf][3], aH + off);
                    ldsm4(Al[mf][0], Al[mf][1], Al[mf][2], Al[mf][3], aL + off);
                }
                #pragma unroll
                for (int nfp = 0; nfp < 2; nfp++) {
                    uint32_t off = ((b_r + nfp * 16) * SPITCH + b_k + ks) * 2;
                    ldsm4(Bh[nfp*2][0], Bh[nfp*2][1], Bh[nfp*2+1][0], Bh[nfp*2+1][1], wH + off);
                    ldsm4(Bl[nfp*2][0], Bl[nfp*2][1], Bl[nfp*2+1][0], Bl[nfp*2+1][1], wL + off);
                }
                #pragma unroll
                for (int mf = 0; mf < 2; mf++)
                    #pragma unroll
                    for (int nf = 0; nf < 4; nf++) {
                        mma_bf16(acc[mf][nf], Ah[mf], Bh[nf]);
                        mma_bf16(acc[mf][nf], Ah[mf], Bl[nf]);
                        mma_bf16(acc[mf][nf], Al[mf], Bh[nf]);
                    }
            }

            if (nx) {
                char* base = dsm + (st ^ 1) * OSTG;
                __nv_bfloat16* sAh = (__nv_bfloat16*)(base);
                __nv_bfloat16* sAl = (__nv_bfloat16*)(base + 5120);
                __nv_bfloat16* sWh = (__nv_bfloat16*)(base + 10240);
                __nv_bfloat16* sWl = (__nv_bfloat16*)(base + 20480);
                *(uint4*)&sAh[arow * SPITCH + akq] = rah;
                *(uint4*)&sAl[arow * SPITCH + akq] = ral;
                *(uint4*)&sWh[wrow * SPITCH + wkq]     = vh0;
                *(uint4*)&sWh[wrow * SPITCH + wkq + 8] = vh1;
                *(uint4*)&sWl[wrow * SPITCH + wkq]     = vl0;
                *(uint4*)&sWl[wrow * SPITCH + wkq + 8] = vl1;
            }
            __syncthreads();
        }

        const float* bias = outp_b + (long)e * OUT_;
        #pragma unroll
        for (int mf = 0; mf < 2; mf++)
            #pragma unroll
            for (int nf = 0; nf < 4; nf++) {
                int n = n0 + wbase + nf * 8 + qq * 2;
                tot[mf][nf][0] += gt * (acc[mf][nf][0] + bias[n]);
                tot[mf][nf][1] += gt * (acc[mf][nf][1] + bias[n + 1]);
                tot[mf][nf][2] += gt * (acc[mf][nf][2] + bias[n]);
                tot[mf][nf][3] += gt * (acc[mf][nf][3] + bias[n + 1]);
            }
    }

    #pragma unroll
    for (int mf = 0; mf < 2; mf++) {
        #pragma unroll
        for (int half = 0; half < 2; half++) {
            int m = m0 + abase + mf * 16 + gq_ + half * 8;
            if (m >= NQ_) continue;
            #pragma unroll
            for (int nf = 0; nf < 4; nf++) {
                int n = n0 + wbase + nf * 8 + qq * 2;
                g_comb[((long)b * NQ_ + m) * OUT_ + n]     = tot[mf][nf][half * 2 + 0];
                g_comb[((long)b * NQ_ + m) * OUT_ + n + 1] = tot[mf][nf][half * 2 + 1];
            }
        }
    }
}

// ---------------- final RMS + scaling ----------------------------------------
__global__ void rms_kernel(const float* __restrict__ final_w,
                           const float* __restrict__ out_gain,
                           float* __restrict__ out) {
    int q = blockIdx.x, b = blockIdx.y;
    int t = threadIdx.x;
    const float* c = g_comb + ((long)b * NQ_ + q) * OUT_;
    float s2 = 0.f;
    for (int o = t; o < OUT_; o += 256) { float v = c[o]; s2 += v * v; }
    __shared__ float red[32];
    s2 = blockReduceSum(s2, red);
    float rs = rsqrtf(s2 / (float)OUT_ + 1e-6f);
    float* orow = out + ((long)b * NQ_ + q) * OUT_;
    for (int o = t; o < OUT_; o += 256) orow[o] = c[o] * rs * final_w[o] * out_gain[o];
}

// ---------------- host driver ------------------------------------------------
extern "C" void kernel_launch(void* const* d_in, const int* in_sizes, int n_in,
                              void* d_out, int out_size) {
    const float* image_embs = (const float*)d_in[0];
    const float* phys       = (const float*)d_in[1];
    const int*   task_ids   = (const int*)d_in[2];
    const int*   elem_ids   = (const int*)d_in[3];
    const float* query      = (const float*)d_in[4];
    const float* ln1_w      = (const float*)d_in[5];
    const float* ln1_b      = (const float*)d_in[6];
    const float* ln1kv_w    = (const float*)d_in[7];
    const float* ln1kv_b    = (const float*)d_in[8];
    const float* attn_in_w  = (const float*)d_in[9];
    const float* attn_in_b  = (const float*)d_in[10];
    const float* attn_out_w = (const float*)d_in[11];
    const float* attn_out_b = (const float*)d_in[12];
    const float* ls1        = (const float*)d_in[13];
    const float* ls2        = (const float*)d_in[14];
    const float* ln2_w      = (const float*)d_in[15];
    const float* ln2_b      = (const float*)d_in[16];
    const float* fc_w       = (const float*)d_in[17];
    const float* fc_b       = (const float*)d_in[18];
    const float* proj_w     = (const float*)d_in[19];
    const float* proj_b     = (const float*)d_in[20];
    const float* outp_w     = (const float*)d_in[21];
    const float* outp_b     = (const float*)d_in[22];
    const float* task_emb   = (const float*)d_in[23];
    const float* elem_emb   = (const float*)d_in[24];
    const float* gate_ln_w  = (const float*)d_in[25];
    const float* gate_ln_b  = (const float*)d_in[26];
    const float* gate_w     = (const float*)d_in[27];
    const float* gate_b     = (const float*)d_in[28];
    const float* output_gain= (const float*)d_in[29];
    const float* final_w    = (const float*)d_in[30];
    (void)in_sizes; (void)n_in; (void)out_size;

    cudaFuncSetAttribute(gemm_k,   cudaFuncAttributeMaxDynamicSharedMemorySize, GTSM);
    cudaFuncSetAttribute(out_gemm, cudaFuncAttributeMaxDynamicSharedMemorySize, OTSM);

    split_all<<<8192, 256>>>(attn_in_w, attn_out_w, fc_w, proj_w, outp_w);   // 1
    gate_kernel<<<B_, 256>>>(image_embs, task_ids, elem_ids, task_emb, elem_emb,
                             gate_ln_w, gate_ln_b, gate_w, gate_b);          // 2
    prep_kernel<<<dim3(320, NP_), 256>>>(query, image_embs, phys,
                                         ln1_w, ln1_b, ln1kv_w, ln1kv_b);    // 3

    for (int l = 0; l < 2; l++) {
        if (l == 1) ln_rows<<<dim3(64, NP_), 256>>>(0, 1, ln1_w, ln1_b, 0, 1);

        GArgs gq = {};
        gq.a_id = 1; gq.c_id = 4;
        gq.wh_off = OFF_ATTNIN; gq.w_stride = 3072L * 1024;
        gq.bias = attn_in_b; gq.bias_stride = 3072;
        gq.ls = nullptr; gq.N = 1024; gq.K = 1024;
        gq.m_is_L = 0; gq.epi = 0; gq.layer = l; gq.packed = 1;
        gemm_k<<<dim3(1, 4, MAXT), 256, GTSM>>>(gq);                         // 4 (l=0, profiled)

        if (l == 1) ln_rows<<<dim3(320, NP_), 256>>>(2, 3, ln1kv_w, ln1kv_b, 1, 1);

        GArgs gkv = {};
        gkv.a_id = 3; gkv.c_id = 5;
        gkv.wh_off = OFF_ATTNIN + 1024L * 1024; gkv.w_stride = 3072L * 1024;
        gkv.bias = attn_in_b + 1024; gkv.bias_stride = 3072;
        gkv.ls = nullptr; gkv.N = 2048; gkv.K = 1024;
        gkv.m_is_L = 1; gkv.epi = 4; gkv.layer = l; gkv.packed = 0;
        gemm_k<<<dim3(5, 8, NP_), 256, GTSM>>>(gkv);

        attn_kernel<<<dim3(16, 16, NP_), 256>>>();

        GArgs go = {};
        go.a_id = 1; go.c_id = 0;
        go.wh_off = OFF_ATTNOUT; go.w_stride = 1024L * 1024;
        go.bias = attn_out_b; go.bias_stride = 1024;
        go.ls = ls1; go.N = 1024; go.K = 1024;
        go.m_is_L = 0; go.epi = 2; go.layer = l; go.packed = 1;
        gemm_k<<<dim3(1, 4, MAXT), 256, GTSM>>>(go);

        ln_rows<<<dim3(64, NP_), 256>>>(0, 1, ln2_w, ln2_b, 0, l);

        GArgs gf = {};
        gf.a_id = 1; gf.c_id = 7;
        gf.wh_off = OFF_FC; gf.w_stride = 4096L * 1024;
        gf.bias = fc_b; gf.bias_stride = 4096;
        gf.ls = nullptr; gf.N = 4096; gf.K = 1024;
        gf.m_is_L = 0; gf.epi = 1; gf.layer = l; gf.packed = 1;
        gemm_k<<<dim3(1, 16, MAXT), 256, GTSM>>>(gf);

        GArgs gp = {};
        gp.a_id = 7; gp.c_id = 0;
        gp.wh_off = OFF_PROJ; gp.w_stride = 1024L * 4096;
        gp.bias = proj_b; gp.bias_stride = 1024;
        gp.ls = ls2; gp.N = 1024; gp.K = 4096;
        gp.m_is_L = 0; gp.epi = 2; gp.layer = l; gp.packed = 1;
        gemm_k<<<dim3(1, 4, MAXT), 256, GTSM>>>(gp);
    }

    out_gemm<<<dim3(3, 32, B_), 256, OTSM>>>(outp_b);
    rms_kernel<<<dim3(NQ_, B_), 256>>>(final_w, output_gain, (float*)d_out);
}

// round 16
// speedup vs baseline: 1.4379x; 1.4379x over previous
#include <cuda_runtime.h>
#include <cuda_bf16.h>
#include <math.h>
#include <stdint.h>

#define E_ 4
#define B_ 8
#define NP_ 96
#define H_ 1024
#define OUT_ 4096
#define NQ_ 144
#define FFH_ 4096
#define MAXT 40

__device__ __constant__ int c_SQ[3] = {64, 48, 32};
__device__ __constant__ int c_L[3]  = {320, 304, 288};
__device__ __constant__ int c_QO[3] = {0, 64, 112};
__device__ __constant__ int c_IO[3] = {0, 256, 512};

// ---------------- scratch ----------------------------------------------------
__device__ float g_gates[B_ * E_];
__device__ float g_x  [NP_ * 64L * H_];
__device__ float g_q  [NP_ * 64L * H_];
__device__ float g_k  [NP_ * 320L * H_];
__device__ float g_v  [NP_ * 320L * H_];
__device__ float g_kv0[NP_ * 320L * H_];
__device__ float g_comb[B_ * (long)NQ_ * OUT_];

// bf16 hi/lo activation buffers
__device__ __nv_bfloat16 g_xnh[NP_ * 64L * H_],  g_xnl[NP_ * 64L * H_];
__device__ __nv_bfloat16 g_kvnh[NP_ * 320L * H_], g_kvnl[NP_ * 320L * H_];
__device__ __nv_bfloat16 g_hh [NP_ * 64L * FFH_], g_hl [NP_ * 64L * FFH_];

// split-bf16 weights (hi/lo)
#define OFF_ATTNIN  0L
#define OFF_ATTNOUT 25165824L
#define OFF_FC      33554432L
#define OFF_PROJ    67108864L
#define OFF_OUTP    100663296L
#define W_TOTAL     117440512L

__device__ __nv_bfloat16 g_wh[W_TOTAL];
__device__ __nv_bfloat16 g_wl[W_TOTAL];

__device__ __forceinline__ float* bufptr(int id) {
    switch (id) {
        case 0: return g_x;  case 2: return g_kv0;
        case 4: return g_q;  case 5: return g_k;
        default: return g_v;
    }
}
__device__ __forceinline__ long bufstride(int id) {
    switch (id) {
        case 0: case 1: case 4: return 64L * H_;
        case 7: return 64L * FFH_;
        default: return 320L * H_;
    }
}
__device__ __forceinline__ __nv_bfloat16* bp16h(int id) {
    switch (id) { case 1: return g_xnh; case 3: return g_kvnh; default: return g_hh; }
}
__device__ __forceinline__ __nv_bfloat16* bp16l(int id) {
    switch (id) { case 1: return g_xnl; case 3: return g_kvnl; default: return g_hl; }
}

// ---------------- inline packed-tile scheduling ------------------------------
__device__ __forceinline__ int tile_row(int zi, int j, int* e_out) {
    int base = 0;
    for (int e = 0; e < 4; e++) {
        int nb = 0;
        #pragma unroll
        for (int b = 0; b < 8; b++) nb += (g_gates[b * 4 + e] != 0.f);
        int rows_e = nb * 144;
        int tiles_e = (rows_e + 63) >> 6;
        if (zi < base + tiles_e) {
            *e_out = e;
            int lrow = (zi - base) * 64 + j;
            if (lrow >= rows_e) return -1;
            int bi = lrow / 144, rr = lrow % 144;
            int b = 0, cnt = 0;
            for (; b < 8; b++) {
                if (g_gates[b * 4 + e] != 0.f) { if (cnt == bi) break; cnt++; }
            }
            int s, r0;
            if (rr < 64)       { s = 0; r0 = rr; }
            else if (rr < 112) { s = 1; r0 = rr - 64; }
            else               { s = 2; r0 = rr - 112; }
            return (e * 24 + b * 3 + s) * 64 + r0;
        }
        base += tiles_e;
    }
    return -2;
}

// ---------------- weight splitting (single launch) ---------------------------
__global__ void split_all(const float* __restrict__ w_attnin,
                          const float* __restrict__ w_attnout,
                          const float* __restrict__ w_fc,
                          const float* __restrict__ w_proj,
                          const float* __restrict__ w_outp) {
    long i = (long)blockIdx.x * blockDim.x + threadIdx.x;
    long stride = (long)gridDim.x * blockDim.x;
    for (; i < W_TOTAL; i += stride) {
        const float* src; long rel;
        if (i < OFF_ATTNOUT)      { src = w_attnin;  rel = i; }
        else if (i < OFF_FC)      { src = w_attnout; rel = i - OFF_ATTNOUT; }
        else if (i < OFF_PROJ)    { src = w_fc;      rel = i - OFF_FC; }
        else if (i < OFF_OUTP)    { src = w_proj;    rel = i - OFF_PROJ; }
        else                      { src = w_outp;    rel = i - OFF_OUTP; }
        float x = src[rel];
        __nv_bfloat16 h = __float2bfloat16(x);
        g_wh[i] = h;
        g_wl[i] = __float2bfloat16(x - __bfloat162float(h));
    }
}

// ---------------- block reductions -------------------------------------------
__device__ __forceinline__ float blockReduceSum(float v, float* sbuf) {
    int t = threadIdx.x;
    for (int o = 16; o; o >>= 1) v += __shfl_down_sync(0xffffffffu, v, o);
    if ((t & 31) == 0) sbuf[t >> 5] = v;
    __syncthreads();
    if (t < 8) {
        v = sbuf[t];
        for (int o = 4; o; o >>= 1) v += __shfl_down_sync(0xffu, v, o);
        if (t == 0) sbuf[0] = v;
    }
    __syncthreads();
    float r = sbuf[0];
    __syncthreads();
    return r;
}
__device__ __forceinline__ float blockReduceMax(float v, float* sbuf) {
    int t = threadIdx.x;
    for (int o = 16; o; o >>= 1) v = fmaxf(v, __shfl_down_sync(0xffffffffu, v, o));
    if ((t & 31) == 0) sbuf[t >> 5] = v;
    __syncthreads();
    if (t < 8) {
        v = sbuf[t];
        for (int o = 4; o; o >>= 1) v = fmaxf(v, __shfl_down_sync(0xffu, v, o));
        if (t == 0) sbuf[0] = v;
    }
    __syncthreads();
    float r = sbuf[0];
    __syncthreads();
    return r;
}

// ---------------- gating -----------------------------------------------------
__global__ void gate_kernel(const float* __restrict__ img,
                            const int* __restrict__ task_ids,
                            const int* __restrict__ elem_ids,
                            const float* __restrict__ task_emb,
                            const float* __restrict__ elem_emb,
                            const float* __restrict__ glw,
                            const float* __restrict__ glb,
                            const float* __restrict__ gw,
                            const float* __restrict__ gb) {
    int b = blockIdx.x;
    int t = threadIdx.x;
    __shared__ float gi[1536];
    __shared__ float sn[1536];
    __shared__ float red[32];
    __shared__ float lg[4];

    float acc0 = 0.f, acc1 = 0.f, acc2 = 0.f, acc3 = 0.f;
    const float* ib = img + (long)b * 576 * H_;
    for (int r = 0; r < 576; r++) {
        const float* row = ib + (long)r * H_;
        acc0 += row[t];        acc1 += row[t + 256];
        acc2 += row[t + 512];  acc3 += row[t + 768];
    }
    const float inv576 = 1.f / 576.f;
    gi[t]       = acc0 * inv576;  gi[t + 256] = acc1 * inv576;
    gi[t + 512] = acc2 * inv576;  gi[t + 768] = acc3 * inv576;
    gi[1024 + t] = task_emb[task_ids[b] * 256 + t];
    gi[1280 + t] = elem_emb[elem_ids[b] * 256 + t];
    __syncthreads();

    float s1 = 0.f;
    for (int d = t; d < 1536; d += 256) s1 += gi[d];
    s1 = blockReduceSum(s1, red);
    float m = s1 / 1536.f;
    float s2 = 0.f;
    for (int d = t; d < 1536; d += 256) { float dd = gi[d] - m; s2 += dd * dd; }
    s2 = blockReduceSum(s2, red);
    float rs = rsqrtf(s2 / 1536.f + 1e-5f);
    for (int d = t; d < 1536; d += 256) sn[d] = (gi[d] - m) * rs * glw[d] + glb[d];
    __syncthreads();

    for (int e = 0; e < 4; e++) {
        float pd = 0.f;
        for (int d = t; d < 1536; d += 256) pd += sn[d] * gw[e * 1536 + d];
        pd = blockReduceSum(pd, red);
        if (t == 0) {
            float l = pd + gb[e];
            lg[e] = fminf(fmaxf(l, -15.f), 15.f);
        }
        __syncthreads();
    }
    if (t == 0) {
        float mx = fmaxf(fmaxf(lg[0], lg[1]), fmaxf(lg[2], lg[3]));
        float pe[4]; float den = 0.f;
        for (int e = 0; e < 4; e++) { pe[e] = expf(lg[e] - mx); den += pe[e]; }
        for (int e = 0; e < 4; e++) pe[e] /= den;
        int i1 = 0;
        for (int e = 1; e < 4; e++) if (pe[e] > pe[i1]) i1 = e;
        int i2 = -1;
        for (int e = 0; e < 4; e++) {
            if (e == i1) continue;
            if (i2 < 0 || pe[e] > pe[i2]) i2 = e;
        }
        float sum2 = pe[i1] + pe[i2] + 1e-9f;
        for (int e = 0; e < 4; e++) g_gates[b * 4 + e] = 0.f;
        g_gates[b * 4 + i1] = pe[i1] / sum2;
        g_gates[b * 4 + i2] = pe[i2] / sum2;
    }
}

// ---------------- fused prep: build kv0/x + layer-0 LN (kv + x) --------------
__global__ void prep_kernel(const float* __restrict__ query,
                            const float* __restrict__ img,
                            const float* __restrict__ pp,
                            const float* __restrict__ ln1_w,
                            const float* __restrict__ ln1_b,
                            const float* __restrict__ ln1kv_w,
                            const float* __restrict__ ln1kv_b) {
    int p = blockIdx.y;
    int e = p / 24, r = p % 24, b = r / 3, s = r % 3;
    if (g_gates[b * 4 + e] == 0.f) return;
    int tk = blockIdx.x;
    int L = c_L[s];
    if (tk >= L) return;
    int sq = c_SQ[s];
    const float* src;
    if (tk < sq) {
        src = query + ((long)e * NQ_ + c_QO[s] + tk) * H_;
    } else {
        int j = c_IO[s] + tk - sq;
        src = (j < 576) ? img + ((long)b * 576 + j) * H_
                        : pp  + ((long)b * 192 + (j - 576)) * H_;
    }
    __shared__ float sx[1024];
    __shared__ float red[32];
    int t = threadIdx.x;
    float s1 = 0.f;
    #pragma unroll
    for (int j = 0; j < 4; j++) { float v = src[t + j * 256]; sx[t + j * 256] = v; s1 += v; }

    float* dst = g_kv0 + (long)p * 320 * H_ + (long)tk * H_;
    #pragma unroll
    for (int j = 0; j < 4; j++) dst[t + j * 256] = sx[t + j * 256];
    if (tk < sq) {
        float* xd = g_x + (long)p * 64 * H_ + (long)tk * H_;
        #pragma unroll
        for (int j = 0; j < 4; j++) xd[t + j * 256] = sx[t + j * 256];
    }

    s1 = blockReduceSum(s1, red);
    float m = s1 / 1024.f;
    float s2 = 0.f;
    #pragma unroll
    for (int j = 0; j < 4; j++) { float d = sx[t + j * 256] - m; s2 += d * d; }
    s2 = blockReduceSum(s2, red);
    float rs = rsqrtf(s2 / 1024.f + 1e-5f);

    const float* wkv = ln1kv_w + (long)(e * 2) * H_;
    const float* bkv = ln1kv_b + (long)(e * 2) * H_;
    long koff = (long)p * 320 * H_ + (long)tk * H_;
    #pragma unroll
    for (int j = 0; j < 4; j++) {
        int d = t + j * 256;
        float val = (sx[d] - m) * rs * wkv[d] + bkv[d];
        __nv_bfloat16 h = __float2bfloat16(val);
        g_kvnh[koff + d] = h;
        g_kvnl[koff + d] = __float2bfloat16(val - __bfloat162float(h));
    }
    if (tk < sq) {
        const float* wq = ln1_w + (long)(e * 2) * H_;
        const float* bq = ln1_b + (long)(e * 2) * H_;
        long xoff = (long)p * 64 * H_ + (long)tk * H_;
        #pragma unroll
        for (int j = 0; j < 4; j++) {
            int d = t + j * 256;
            float val = (sx[d] - m) * rs * wq[d] + bq[d];
            __nv_bfloat16 h = __float2bfloat16(val);
            g_xnh[xoff + d] = h;
            g_xnl[xoff + d] = __float2bfloat16(val - __bfloat162float(h));
        }
    }
}

// ---------------- row LayerNorm → bf16 hi/lo ---------------------------------
__global__ void ln_rows(int src, int dst,
                        const float* __restrict__ wbase,
                        const float* __restrict__ bbase,
                        int m_is_L, int layer) {
    int p = blockIdx.y;
    int e = p / 24, r = p % 24, b = r / 3, s = r % 3;
    if (g_gates[b * 4 + e] == 0.f) return;
    int M = m_is_L ? c_L[s] : c_SQ[s];
    int row = blockIdx.x;
    if (row >= M) return;
    const float* x = bufptr(src) + (long)p * bufstride(src) + (long)row * H_;
    long doff = (long)p * bufstride(dst) + (long)row * H_;
    __nv_bfloat16* yh = bp16h(dst) + doff;
    __nv_bfloat16* yl = bp16l(dst) + doff;
    const float* w  = wbase + (long)(e * 2 + layer) * H_;
    const float* bb = bbase + (long)(e * 2 + layer) * H_;
    __shared__ float sx[1024];
    __shared__ float red[32];
    int t = threadIdx.x;
    float s1 = 0.f;
    #pragma unroll
    for (int j = 0; j < 4; j++) { float v = x[t + j * 256]; sx[t + j * 256] = v; s1 += v; }
    s1 = blockReduceSum(s1, red);
    float m = s1 / 1024.f;
    float s2 = 0.f;
    #pragma unroll
    for (int j = 0; j < 4; j++) { float d = sx[t + j * 256] - m; s2 += d * d; }
    s2 = blockReduceSum(s2, red);
    float rs = rsqrtf(s2 / 1024.f + 1e-5f);
    #pragma unroll
    for (int j = 0; j < 4; j++) {
        int d = t + j * 256;
        float val = (sx[d] - m) * rs * w[d] + bb[d];
        __nv_bfloat16 h = __float2bfloat16(val);
        yh[d] = h;
        yl[d] = __float2bfloat16(val - __bfloat162float(h));
    }
}

// ---------------- tensor-core GEMM: BM=64 BN=128, cp.async, 2-stage ----------
#define SPITCH 40
#define STG_BYTES 30720
#define TSM_TOTAL (2 * STG_BYTES)

struct GArgs {
    int a_id; int c_id;
    long wh_off; long w_stride;
    const float* bias; long bias_stride;
    const float* ls;
    int N; int K;
    int m_is_L;
    int epi;     // 0 fp32 store, 1 gelu->bf16hi/lo, 2 C += ls*(c+bias), 4 kv-split
    int layer;
    int packed;
};

__device__ __forceinline__ void mma_bf16(float* d, const uint32_t* a, const uint32_t* b) {
    asm volatile(
        "mma.sync.aligned.m16n8k16.row.col.f32.bf16.bf16.f32 "
        "{%0,%1,%2,%3}, {%4,%5,%6,%7}, {%8,%9}, {%0,%1,%2,%3};\n"
        : "+f"(d[0]), "+f"(d[1]), "+f"(d[2]), "+f"(d[3])
        : "r"(a[0]), "r"(a[1]), "r"(a[2]), "r"(a[3]), "r"(b[0]), "r"(b[1]));
}
__device__ __forceinline__ void ldsm4(uint32_t& r0, uint32_t& r1, uint32_t& r2, uint32_t& r3,
                                      uint32_t addr) {
    asm volatile("ldmatrix.sync.aligned.m8n8.x4.shared.b16 {%0,%1,%2,%3}, [%4];"
                 : "=r"(r0), "=r"(r1), "=r"(r2), "=r"(r3) : "r"(addr));
}
__device__ __forceinline__ void split8(float4 f0, float4 f1, uint4& hi, uint4& lo) {
    __nv_bfloat162 h0 = __floats2bfloat162_rn(f0.x, f0.y);
    __nv_bfloat162 h1 = __floats2bfloat162_rn(f0.z, f0.w);
    __nv_bfloat162 h2 = __floats2bfloat162_rn(f1.x, f1.y);
    __nv_bfloat162 h3 = __floats2bfloat162_rn(f1.z, f1.w);
    float2 a0 = __bfloat1622float2(h0), a1 = __bfloat1622float2(h1);
    float2 a2 = __bfloat1622float2(h2), a3 = __bfloat1622float2(h3);
    __nv_bfloat162 l0 = __floats2bfloat162_rn(f0.x - a0.x, f0.y - a0.y);
    __nv_bfloat162 l1 = __floats2bfloat162_rn(f0.z - a1.x, f0.w - a1.y);
    __nv_bfloat162 l2 = __floats2bfloat162_rn(f1.x - a2.x, f1.y - a2.y);
    __nv_bfloat162 l3 = __floats2bfloat162_rn(f1.z - a3.x, f1.w - a3.y);
    hi.x = *(uint32_t*)&h0; hi.y = *(uint32_t*)&h1; hi.z = *(uint32_t*)&h2; hi.w = *(uint32_t*)&h3;
    lo.x = *(uint32_t*)&l0; lo.y = *(uint32_t*)&l1; lo.z = *(uint32_t*)&l2; lo.w = *(uint32_t*)&l3;
}

__device__ __forceinline__ void cpa16(uint32_t dst, const void* src) {
    asm volatile("cp.async.cg.shared.global [%0], [%1], 16;" :: "r"(dst), "l"(src));
}
__device__ __forceinline__ void cpa16z(uint32_t dst) {
    asm volatile("cp.async.cg.shared.global [%0], [%1], 16, 0;"
                 :: "r"(dst), "l"((const void*)g_wh));
}
#define CP_COMMIT asm volatile("cp.async.commit_group;" ::: "memory")
#define CP_WAIT1  asm volatile("cp.async.wait_group 1;" ::: "memory")
#define CP_WAIT0  asm volatile("cp.async.wait_group 0;" ::: "memory")

__global__ void __launch_bounds__(256) gemm_k(GArgs g) {
    int zi = blockIdx.z;
    int e = 0, p = 0, M = 64, m0 = 0;
    long pbaseA = 0;

    if (g.packed) {
        int probe = tile_row(zi, 0, &e);
        if (probe == -2) return;
    } else {
        p = zi;
        e = p / 24;
        int r = p % 24, b = r / 3, s = r % 3;
        if (g_gates[b * 4 + e] == 0.f) return;
        M = g.m_is_L ? c_L[s] : c_SQ[s];
        m0 = blockIdx.x * 64;
        if (m0 >= M) return;
        pbaseA = (long)p * bufstride(g.a_id);
    }
    int n0 = blockIdx.y * 128;

    const __nv_bfloat16* Wh = g_wh + g.wh_off + (long)(e * 2 + g.layer) * g.w_stride;
    const __nv_bfloat16* Wl = g_wl + g.wh_off + (long)(e * 2 + g.layer) * g.w_stride;
    const float* bias = g.bias + (long)(e * 2 + g.layer) * g.bias_stride;

    extern __shared__ char dsm[];
    uint32_t smem_u = (uint32_t)__cvta_generic_to_shared(dsm);

    int tid = threadIdx.x;
    // A loader: row = tid>>2 (64 rows), 16B chunk = (tid&3)*8 elems
    int arow = tid >> 2, akq = (tid & 3) << 3;
    const __nv_bfloat16* ahrow = nullptr;
    const __nv_bfloat16* alrow = nullptr;
    if (g.packed) {
        int e2;
        int rm = tile_row(zi, arow, &e2);
        if (rm >= 0) {
            long aoff = (long)rm * g.K + akq;
            ahrow = bp16h(g.a_id) + aoff;
            alrow = bp16l(g.a_id) + aoff;
        }
    } else if (m0 + arow < M) {
        long aoff = pbaseA + (long)(m0 + arow) * g.K + akq;
        ahrow = bp16h(g.a_id) + aoff;
        alrow = bp16l(g.a_id) + aoff;
    }
    // W loader: row = tid>>1 (128 rows), 32B = two 16B chunks at (tid&1)*16
    int wrow = tid >> 1, wkq = (tid & 1) << 4;
    const __nv_bfloat16* whp = Wh + (long)(n0 + wrow) * g.K + wkq;
    const __nv_bfloat16* wlp = Wl + (long)(n0 + wrow) * g.K + wkq;

    uint32_t sA_off = (uint32_t)(arow * SPITCH + akq) * 2;
    uint32_t sW_off = (uint32_t)(wrow * SPITCH + wkq) * 2;

    // compute mapping: 8 warps (2 x 4), warp tile 32x32
    int lane = tid & 31, w = tid >> 5;
    int gq_ = lane >> 2, qq = lane & 3;
    int wm = w & 1, wn = w >> 1;
    int abase = wm * 32, wbase = wn * 32;

    int lr = lane & 7, tq = lane >> 3;
    int a_r = abase + ((tq & 1) << 3) + lr;
    int a_k = (tq >> 1) << 3;
    int b_r = wbase + ((tq >> 1) << 3) + lr;
    int b_k = (tq & 1) << 3;

    float acc[2][4][4];
    #pragma unroll
    for (int i = 0; i < 2; i++)
        #pragma unroll
        for (int j = 0; j < 4; j++)
            #pragma unroll
            for (int k = 0; k < 4; k++) acc[i][j][k] = 0.f;

    int nc = g.K >> 5;

    auto prefetch = [&](int c, int st) {
        uint32_t sb = smem_u + st * STG_BYTES;
        long ko = (long)c << 5;
        if (ahrow) {
            cpa16(sb + sA_off, ahrow + ko);
            cpa16(sb + 5120 + sA_off, alrow + ko);
        } else {
            cpa16z(sb + sA_off);
            cpa16z(sb + 5120 + sA_off);
        }
        uint32_t wb = sb + 10240 + sW_off;
        cpa16(wb,          whp + ko);
        cpa16(wb + 16,     whp + ko + 8);
        cpa16(wb + 10240,      wlp + ko);
        cpa16(wb + 10240 + 16, wlp + ko + 8);
        CP_COMMIT;
    };

    prefetch(0, 0);
    if (nc > 1) prefetch(1, 1);

    for (int c = 0; c < nc; c++) {
        int st = c & 1;
        if (c == nc - 1) { CP_WAIT0; } else { CP_WAIT1; }
        __syncthreads();

        uint32_t aH = smem_u + st * STG_BYTES;
        uint32_t aL = aH + 5120;
        uint32_t wH = aH + 10240;
        uint32_t wL = aH + 20480;

        #pragma unroll
        for (int ks = 0; ks < 32; ks += 16) {
            uint32_t Ah[2][4], Al[2][4], Bh[4][2], Bl[4][2];
            #pragma unroll
            for (int mf = 0; mf < 2; mf++) {
                uint32_t off = ((a_r + mf * 16) * SPITCH + a_k + ks) * 2;
                ldsm4(Ah[mf][0], Ah[mf][1], Ah[mf][2], Ah[mf][3], aH + off);
                ldsm4(Al[mf][0], Al[mf][1], Al[mf][2], Al[mf][3], aL + off);
            }
            #pragma unroll
            for (int nfp = 0; nfp < 2; nfp++) {
                uint32_t off = ((b_r + nfp * 16) * SPITCH + b_k + ks) * 2;
                ldsm4(Bh[nfp*2][0], Bh[nfp*2][1], Bh[nfp*2+1][0], Bh[nfp*2+1][1], wH + off);
                ldsm4(Bl[nfp*2][0], Bl[nfp*2][1], Bl[nfp*2+1][0], Bl[nfp*2+1][1], wL + off);
            }
            #pragma unroll
            for (int mf = 0; mf < 2; mf++)
                #pragma unroll
                for (int nf = 0; nf < 4; nf++) {
                    mma_bf16(acc[mf][nf], Ah[mf], Bh[nf]);
                    mma_bf16(acc[mf][nf], Ah[mf], Bl[nf]);
                    mma_bf16(acc[mf][nf], Al[mf], Bh[nf]);
                }
        }
        __syncthreads();
        if (c + 2 < nc) prefetch(c + 2, st);
    }

    // epilogue
    float* C = bufptr(g.c_id);
    __nv_bfloat16* Ch = bp16h(g.c_id);
    __nv_bfloat16* Cl = bp16l(g.c_id);
    long pbaseC = g.packed ? 0 : (long)p * bufstride(g.c_id);
    long pbaseKV = (long)p * 320L * H_;
    const float* lsp = (g.epi == 2) ? (g.ls + (long)(e * 2 + g.layer) * H_) : nullptr;

    #pragma unroll
    for (int mf = 0; mf < 2; mf++) {
        #pragma unroll
        for (int half = 0; half < 2; half++) {
            int ml = abase + mf * 16 + gq_ + half * 8;
            long rowoff;
            if (g.packed) {
                int e2;
                int rm = tile_row(zi, ml, &e2);
                if (rm < 0) continue;
                rowoff = (long)rm * g.N;
            } else {
                int m = m0 + ml;
                if (m >= M) continue;
                rowoff = pbaseC + (long)m * g.N;
                if (g.epi == 4) rowoff = pbaseKV + (long)m * (long)H_;
            }
            #pragma unroll
            for (int nf = 0; nf < 4; nf++) {
                int n = n0 + wbase + nf * 8 + qq * 2;
                float v0 = acc[mf][nf][half * 2 + 0] + bias[n];
                float v1 = acc[mf][nf][half * 2 + 1] + bias[n + 1];
                if (g.epi == 0) {
                    long idx = rowoff + n;
                    C[idx] = v0; C[idx + 1] = v1;
                } else if (g.epi == 1) {
                    long idx = rowoff + n;
                    float t0 = v0 * 0.5f * (1.f + erff(v0 * 0.70710678118654752f));
                    float t1 = v1 * 0.5f * (1.f + erff(v1 * 0.70710678118654752f));
                    __nv_bfloat16 h0 = __float2bfloat16(t0);
                    __nv_bfloat16 h1 = __float2bfloat16(t1);
                    Ch[idx] = h0;     Ch[idx + 1] = h1;
                    Cl[idx]     = __float2bfloat16(t0 - __bfloat162float(h0));
                    Cl[idx + 1] = __float2bfloat16(t1 - __bfloat162float(h1));
                } else if (g.epi == 2) {
                    long idx = rowoff + n;
                    C[idx]     += lsp[n] * v0;
                    C[idx + 1] += lsp[n + 1] * v1;
                } else {
                    float* dst = (n < 1024) ? g_k : g_v;
                    long idx = rowoff + (n & 1023);
                    dst[idx] = v0; dst[idx + 1] = v1;
                }
            }
        }
    }
}

// ---------------- attention: 4 q-rows per block ------------------------------
__global__ void attn_kernel() {
    int p = blockIdx.z;
    int e = p / 24, r = p % 24, b = r / 3, s = r % 3;
    if (g_gates[b * 4 + e] == 0.f) return;
    int sq = c_SQ[s];
    int r0 = blockIdx.x * 4;
    if (r0 >= sq) return;
    int L = c_L[s];
    int h = blockIdx.y;
    int t = threadIdx.x;

    __shared__ float sc[4][320];
    __shared__ float qv[4][64];
    __shared__ float red[32];
    __shared__ float cbuf[4][4][64];
    __shared__ float inv[4];

    const float* Qb = g_q + (long)p * 64 * H_ + (long)r0 * H_ + h * 64;
    const float* K  = g_k + (long)p * 320 * H_ + h * 64;
    const float* V  = g_v + (long)p * 320 * H_ + h * 64;

    qv[t >> 6][t & 63] = Qb[(long)(t >> 6) * H_ + (t & 63)];
    __syncthreads();

    for (int k = t; k < L; k += 256) {
        const float* kr = K + (long)k * H_;
        float d0 = 0.f, d1 = 0.f, d2 = 0.f, d3 = 0.f;
        #pragma unroll
        for (int dd = 0; dd < 64; dd++) {
            float kvv = kr[dd];
            d0 += qv[0][dd] * kvv;
            d1 += qv[1][dd] * kvv;
            d2 += qv[2][dd] * kvv;
            d3 += qv[3][dd] * kvv;
        }
        sc[0][k] = d0 * 0.125f;
        sc[1][k] = d1 * 0.125f;
        sc[2][k] = d2 * 0.125f;
        sc[3][k] = d3 * 0.125f;
    }
    __syncthreads();

    for (int rr = 0; rr < 4; rr++) {
        float mx = -1e30f;
        for (int k = t; k < L; k += 256) mx = fmaxf(mx, sc[rr][k]);
        mx = blockReduceMax(mx, red);
        float sum = 0.f;
        for (int k = t; k < L; k += 256) {
            float ev = expf(sc[rr][k] - mx);
            sc[rr][k] = ev;
            sum += ev;
        }
        sum = blockReduceSum(sum, red);
        if (t == 0) inv[rr] = 1.f / sum;
        __syncthreads();
    }

    int d = t & 63, ch = t >> 6;
    float a0 = 0.f, a1 = 0.f, a2 = 0.f, a3 = 0.f;
    for (int k = ch; k < L; k += 4) {
        float vv = V[(long)k * H_ + d];
        a0 += sc[0][k] * vv;
        a1 += sc[1][k] * vv;
        a2 += sc[2][k] * vv;
        a3 += sc[3][k] * vv;
    }
    cbuf[ch][0][d] = a0;
    cbuf[ch][1][d] = a1;
    cbuf[ch][2][d] = a2;
    cbuf[ch][3][d] = a3;
    __syncthreads();

    {
        int rr = t >> 6, dd = t & 63;
        float o = (cbuf[0][rr][dd] + cbuf[1][rr][dd] + cbuf[2][rr][dd] + cbuf[3][rr][dd]) * inv[rr];
        long ooff = (long)p * 64 * H_ + (long)(r0 + rr) * H_ + h * 64 + dd;
        __nv_bfloat16 oh = __float2bfloat16(o);
        g_xnh[ooff] = oh;
        g_xnl[ooff] = __float2bfloat16(o - __bfloat162float(oh));
    }
}

// ---------------- expert-weighted output projection (legacy path) ------------
__global__ void __launch_bounds__(256) out_gemm(const float* __restrict__ outp_b) {
    int b = blockIdx.z;
    int m0 = blockIdx.x * 64;
    int n0 = blockIdx.y * 128;

    extern __shared__ char dsm[];
    uint32_t smem_u = (uint32_t)__cvta_generic_to_shared(dsm);

    int tid = threadIdx.x;
    int arow = tid >> 2, akq = (tid & 3) << 3;
    int wrow = tid >> 1, wkq = (tid & 1) << 4;
    int lane = tid & 31, w = tid >> 5;
    int gq_ = lane >> 2, qq = lane & 3;
    int wm = w & 1, wn = w >> 1;
    int abase = wm * 32, wbase = wn * 32;

    int lr = lane & 7, tq = lane >> 3;
    int a_r = abase + ((tq & 1) << 3) + lr;
    int a_k = (tq >> 1) << 3;
    int b_r = wbase + ((tq >> 1) << 3) + lr;
    int b_k = (tq & 1) << 3;

    int qg = m0 + arow;
    bool aval = qg < NQ_;
    int s = 0, lrq = 0;
    if (aval) {
        s = (qg < 64) ? 0 : ((qg < 112) ? 1 : 2);
        lrq = qg - c_QO[s];
    }

    float tot[2][4][4];
    #pragma unroll
    for (int i = 0; i < 2; i++)
        #pragma unroll
        for (int j = 0; j < 4; j++)
            #pragma unroll
            for (int k = 0; k < 4; k++) tot[i][j][k] = 0.f;

    for (int e = 0; e < 4; e++) {
        float gt = g_gates[b * 4 + e];
        if (gt == 0.f) continue;
        const float* aptr = g_x + ((long)(e * 24 + b * 3 + s) * 64 + lrq) * H_ + akq;
        long wb = OFF_OUTP + (long)e * OUT_ * H_ + (long)(n0 + wrow) * H_ + wkq;
        const __nv_bfloat16* whp = g_wh + wb;
        const __nv_bfloat16* wlp = g_wl + wb;

        float acc[2][4][4];
        #pragma unroll
        for (int i = 0; i < 2; i++)
            #pragma unroll
            for (int j = 0; j < 4; j++)
                #pragma unroll
                for (int k = 0; k < 4; k++) acc[i][j][k] = 0.f;

        float4 f0, f1;
        uint4 rah, ral, vh0, vh1, vl0, vl1;
        uint4 zz = make_uint4(0u, 0u, 0u, 0u);

        f0 = f1 = make_float4(0.f, 0.f, 0.f, 0.f);
        if (aval) { f0 = *(const float4*)(aptr); f1 = *(const float4*)(aptr + 4); }
        split8(f0, f1, rah, ral);
        if (!aval) { rah = zz; ral = zz; }
        vh0 = *(const uint4*)(whp);  vh1 = *(const uint4*)(whp + 8);
        vl0 = *(const uint4*)(wlp);  vl1 = *(const uint4*)(wlp + 8);

        __syncthreads();
        {
            __nv_bfloat16* sAh = (__nv_bfloat16*)(dsm);
            __nv_bfloat16* sAl = (__nv_bfloat16*)(dsm + 5120);
            __nv_bfloat16* sWh = (__nv_bfloat16*)(dsm + 10240);
            __nv_bfloat16* sWl = (__nv_bfloat16*)(dsm + 20480);
            *(uint4*)&sAh[arow * SPITCH + akq] = rah;
            *(uint4*)&sAl[arow * SPITCH + akq] = ral;
            *(uint4*)&sWh[wrow * SPITCH + wkq]     = vh0;
            *(uint4*)&sWh[wrow * SPITCH + wkq + 8] = vh1;
            *(uint4*)&sWl[wrow * SPITCH + wkq]     = vl0;
            *(uint4*)&sWl[wrow * SPITCH + wkq + 8] = vl1;
        }
        __syncthreads();

        const int nc = H_ >> 5;
        for (int c = 0; c < nc; c++) {
            int st = c & 1;
            bool nx = (c + 1 < nc);
            if (nx) {
                long off = (long)(c + 1) << 5;
                f0 = f1 = make_float4(0.f, 0.f, 0.f, 0.f);
                if (aval) { f0 = *(const float4*)(aptr + off); f1 = *(const float4*)(aptr + off + 4); }
                split8(f0, f1, rah, ral);
                if (!aval) { rah = zz; ral = zz; }
                vh0 = *(const uint4*)(whp + off);  vh1 = *(const uint4*)(whp + off + 8);
                vl0 = *(const uint4*)(wlp + off);  vl1 = *(const uint4*)(wlp + off + 8);
            }

            uint32_t aH = smem_u + st * STG_BYTES;
            uint32_t aL = aH + 5120;
            uint32_t wH = aH + 10240;
            uint32_t wL = aH + 20480;

            #pragma unroll
            for (int ks = 0; ks < 32; ks += 16) {
                uint32_t Ah[2][4], Al[2][4], Bh[4][2], Bl[4][2];
                #pragma unroll
                for (int mf = 0; mf < 2; mf++) {
                    uint32_t off = ((a_r + mf * 16) * SPITCH + a_k + ks) * 2;
                    ldsm4(Ah[mf][0], Ah[mf][1], Ah[mf][2], Ah[mf][3], aH + off);
                    ldsm4(Al[mf][0], Al[mf][1], Al[mf][2], Al[mf][3], aL + off);
                }
                #pragma unroll
                for (int nfp = 0; nfp < 2; nfp++) {
                    uint32_t off = ((b_r + nfp * 16) * SPITCH + b_k + ks) * 2;
                    ldsm4(Bh[nfp*2][0], Bh[nfp*2][1], Bh[nfp*2+1][0], Bh[nfp*2+1][1], wH + off);
                    ldsm4(Bl[nfp*2][0], Bl[nfp*2][1], Bl[nfp*2+1][0], Bl[nfp*2+1][1], wL + off);
                }
                #pragma unroll
                for (int mf = 0; mf < 2; mf++)
                    #pragma unroll
                    for (int nf = 0; nf < 4; nf++) {
                        mma_bf16(acc[mf][nf], Ah[mf], Bh[nf]);
                        mma_bf16(acc[mf][nf], Ah[mf], Bl[nf]);
                        mma_bf16(acc[mf][nf], Al[mf], Bh[nf]);
                    }
            }

            if (nx) {
                char* base = dsm + (st ^ 1) * STG_BYTES;
                __nv_bfloat16* sAh = (__nv_bfloat16*)(base);
                __nv_bfloat16* sAl = (__nv_bfloat16*)(base + 5120);
                __nv_bfloat16* sWh = (__nv_bfloat16*)(base + 10240);
                __nv_bfloat16* sWl = (__nv_bfloat16*)(base + 20480);
                *(uint4*)&sAh[arow * SPITCH + akq] = rah;
                *(uint4*)&sAl[arow * SPITCH + akq] = ral;
                *(uint4*)&sWh[wrow * SPITCH + wkq]     = vh0;
                *(uint4*)&sWh[wrow * SPITCH + wkq + 8] = vh1;
                *(uint4*)&sWl[wrow * SPITCH + wkq]     = vl0;
                *(uint4*)&sWl[wrow * SPITCH + wkq + 8] = vl1;
            }
            __syncthreads();
        }

        const float* bias = outp_b + (long)e * OUT_;
        #pragma unroll
        for (int mf = 0; mf < 2; mf++)
            #pragma unroll
            for (int nf = 0; nf < 4; nf++) {
                int n = n0 + wbase + nf * 8 + qq * 2;
                tot[mf][nf][0] += gt * (acc[mf][nf][0] + bias[n]);
                tot[mf][nf][1] += gt * (acc[mf][nf][1] + bias[n + 1]);
                tot[mf][nf][2] += gt * (acc[mf][nf][2] + bias[n]);
                tot[mf][nf][3] += gt * (acc[mf][nf][3] + bias[n + 1]);
            }
    }

    #pragma unroll
    for (int mf = 0; mf < 2; mf++) {
        #pragma unroll
        for (int half = 0; half < 2; half++) {
            int m = m0 + abase + mf * 16 + gq_ + half * 8;
            if (m >= NQ_) continue;
            #pragma unroll
            for (int nf = 0; nf < 4; nf++) {
                int n = n0 + wbase + nf * 8 + qq * 2;
                g_comb[((long)b * NQ_ + m) * OUT_ + n]     = tot[mf][nf][half * 2 + 0];
                g_comb[((long)b * NQ_ + m) * OUT_ + n + 1] = tot[mf][nf][half * 2 + 1];
            }
        }
    }
}

// ---------------- final RMS + scaling ----------------------------------------
__global__ void rms_kernel(const float* __restrict__ final_w,
                           const float* __restrict__ out_gain,
                           float* __restrict__ out) {
    int q = blockIdx.x, b = blockIdx.y;
    int t = threadIdx.x;
    const float* c = g_comb + ((long)b * NQ_ + q) * OUT_;
    float s2 = 0.f;
    for (int o = t; o < OUT_; o += 256) { float v = c[o]; s2 += v * v; }
    __shared__ float red[32];
    s2 = blockReduceSum(s2, red);
    float rs = rsqrtf(s2 / (float)OUT_ + 1e-6f);
    float* orow = out + ((long)b * NQ_ + q) * OUT_;
    for (int o = t; o < OUT_; o += 256) orow[o] = c[o] * rs * final_w[o] * out_gain[o];
}

// ---------------- host driver ------------------------------------------------
extern "C" void kernel_launch(void* const* d_in, const int* in_sizes, int n_in,
                              void* d_out, int out_size) {
    const float* image_embs = (const float*)d_in[0];
    const float* phys       = (const float*)d_in[1];
    const int*   task_ids   = (const int*)d_in[2];
    const int*   elem_ids   = (const int*)d_in[3];
    const float* query      = (const float*)d_in[4];
    const float* ln1_w      = (const float*)d_in[5];
    const float* ln1_b      = (const float*)d_in[6];
    const float* ln1kv_w    = (const float*)d_in[7];
    const float* ln1kv_b    = (const float*)d_in[8];
    const float* attn_in_w  = (const float*)d_in[9];
    const float* attn_in_b  = (const float*)d_in[10];
    const float* attn_out_w = (const float*)d_in[11];
    const float* attn_out_b = (const float*)d_in[12];
    const float* ls1        = (const float*)d_in[13];
    const float* ls2        = (const float*)d_in[14];
    const float* ln2_w      = (const float*)d_in[15];
    const float* ln2_b      = (const float*)d_in[16];
    const float* fc_w       = (const float*)d_in[17];
    const float* fc_b       = (const float*)d_in[18];
    const float* proj_w     = (const float*)d_in[19];
    const float* proj_b     = (const float*)d_in[20];
    const float* outp_w     = (const float*)d_in[21];
    const float* outp_b     = (const float*)d_in[22];
    const float* task_emb   = (const float*)d_in[23];
    const float* elem_emb   = (const float*)d_in[24];
    const float* gate_ln_w  = (const float*)d_in[25];
    const float* gate_ln_b  = (const float*)d_in[26];
    const float* gate_w     = (const float*)d_in[27];
    const float* gate_b     = (const float*)d_in[28];
    const float* output_gain= (const float*)d_in[29];
    const float* final_w    = (const float*)d_in[30];
    (void)in_sizes; (void)n_in; (void)out_size;

    cudaFuncSetAttribute(gemm_k,   cudaFuncAttributeMaxDynamicSharedMemorySize, TSM_TOTAL);
    cudaFuncSetAttribute(out_gemm, cudaFuncAttributeMaxDynamicSharedMemorySize, TSM_TOTAL);

    split_all<<<8192, 256>>>(attn_in_w, attn_out_w, fc_w, proj_w, outp_w);   // 1
    gate_kernel<<<B_, 256>>>(image_embs, task_ids, elem_ids, task_emb, elem_emb,
                             gate_ln_w, gate_ln_b, gate_w, gate_b);          // 2
    prep_kernel<<<dim3(320, NP_), 256>>>(query, image_embs, phys,
                                         ln1_w, ln1_b, ln1kv_w, ln1kv_b);    // 3

    for (int l = 0; l < 2; l++) {
        if (l == 1) ln_rows<<<dim3(64, NP_), 256>>>(0, 1, ln1_w, ln1_b, 0, 1);

        GArgs gq = {};
        gq.a_id = 1; gq.c_id = 4;
        gq.wh_off = OFF_ATTNIN; gq.w_stride = 3072L * 1024;
        gq.bias = attn_in_b; gq.bias_stride = 3072;
        gq.ls = nullptr; gq.N = 1024; gq.K = 1024;
        gq.m_is_L = 0; gq.epi = 0; gq.layer = l; gq.packed = 1;
        gemm_k<<<dim3(1, 8, MAXT), 256, TSM_TOTAL>>>(gq);                    // 4 (l=0, profiled)

        if (l == 1) ln_rows<<<dim3(320, NP_), 256>>>(2, 3, ln1kv_w, ln1kv_b, 1, 1);

        GArgs gkv = {};
        gkv.a_id = 3; gkv.c_id = 5;
        gkv.wh_off = OFF_ATTNIN + 1024L * 1024; gkv.w_stride = 3072L * 1024;
        gkv.bias = attn_in_b + 1024; gkv.bias_stride = 3072;
        gkv.ls = nullptr; gkv.N = 2048; gkv.K = 1024;
        gkv.m_is_L = 1; gkv.epi = 4; gkv.layer = l; gkv.packed = 0;
        gemm_k<<<dim3(5, 16, NP_), 256, TSM_TOTAL>>>(gkv);

        attn_kernel<<<dim3(16, 16, NP_), 256>>>();

        GArgs go = {};
        go.a_id = 1; go.c_id = 0;
        go.wh_off = OFF_ATTNOUT; go.w_stride = 1024L * 1024;
        go.bias = attn_out_b; go.bias_stride = 1024;
        go.ls = ls1; go.N = 1024; go.K = 1024;
        go.m_is_L = 0; go.epi = 2; go.layer = l; go.packed = 1;
        gemm_k<<<dim3(1, 8, MAXT), 256, TSM_TOTAL>>>(go);

        ln_rows<<<dim3(64, NP_), 256>>>(0, 1, ln2_w, ln2_b, 0, l);

        GArgs gf = {};
        gf.a_id = 1; gf.c_id = 7;
        gf.wh_off = OFF_FC; gf.w_stride = 4096L * 1024;
        gf.bias = fc_b; gf.bias_stride = 4096;
        gf.ls = nullptr; gf.N = 4096; gf.K = 1024;
        gf.m_is_L = 0; gf.epi = 1; gf.layer = l; gf.packed = 1;
        gemm_k<<<dim3(1, 32, MAXT), 256, TSM_TOTAL>>>(gf);

        GArgs gp = {};
        gp.a_id = 7; gp.c_id = 0;
        gp.wh_off = OFF_PROJ; gp.w_stride = 1024L * 4096;
        gp.bias = proj_b; gp.bias_stride = 1024;
        gp.ls = ls2; gp.N = 1024; gp.K = 4096;
        gp.m_is_L = 0; gp.epi = 2; gp.layer = l; gp.packed = 1;
        gemm_k<<<dim3(1, 8, MAXT), 256, TSM_TOTAL>>>(gp);
    }

    out_gemm<<<dim3(3, 32, B_), 256, TSM_TOTAL>>>(outp_b);
    rms_kernel<<<dim3(NQ_, B_), 256>>>(final_w, output_gain, (float*)d_out);
}

// round 17
// speedup vs baseline: 1.4473x; 1.0065x over previous
#include <cuda_runtime.h>
#include <cuda_bf16.h>
#include <math.h>
#include <stdint.h>

#define E_ 4
#define B_ 8
#define NP_ 96
#define H_ 1024
#define OUT_ 4096
#define NQ_ 144
#define FFH_ 4096
#define MAXT 40

__device__ __constant__ int c_SQ[3] = {64, 48, 32};
__device__ __constant__ int c_L[3]  = {320, 304, 288};
__device__ __constant__ int c_QO[3] = {0, 64, 112};
__device__ __constant__ int c_IO[3] = {0, 256, 512};

// ---------------- scratch ----------------------------------------------------
__device__ float g_gates[B_ * E_];
__device__ float g_x  [NP_ * 64L * H_];
__device__ float g_q  [NP_ * 64L * H_];
__device__ float g_k  [NP_ * 320L * H_];
__device__ float g_v  [NP_ * 320L * H_];
__device__ float g_kv0[NP_ * 320L * H_];
__device__ float g_comb[B_ * (long)NQ_ * OUT_];

// bf16 hi/lo activation buffers
__device__ __nv_bfloat16 g_xnh[NP_ * 64L * H_],  g_xnl[NP_ * 64L * H_];
__device__ __nv_bfloat16 g_kvnh[NP_ * 320L * H_], g_kvnl[NP_ * 320L * H_];
__device__ __nv_bfloat16 g_hh [NP_ * 64L * FFH_], g_hl [NP_ * 64L * FFH_];

// split-bf16 weights (hi/lo)
#define OFF_ATTNIN  0L
#define OFF_ATTNOUT 25165824L
#define OFF_FC      33554432L
#define OFF_PROJ    67108864L
#define OFF_OUTP    100663296L
#define W_TOTAL     117440512L

__device__ __nv_bfloat16 g_wh[W_TOTAL];
__device__ __nv_bfloat16 g_wl[W_TOTAL];

__device__ __forceinline__ float* bufptr(int id) {
    switch (id) {
        case 0: return g_x;  case 2: return g_kv0;
        case 4: return g_q;  case 5: return g_k;
        default: return g_v;
    }
}
__device__ __forceinline__ long bufstride(int id) {
    switch (id) {
        case 0: case 1: case 4: return 64L * H_;
        case 7: return 64L * FFH_;
        default: return 320L * H_;
    }
}
__device__ __forceinline__ __nv_bfloat16* bp16h(int id) {
    switch (id) { case 1: return g_xnh; case 3: return g_kvnh; default: return g_hh; }
}
__device__ __forceinline__ __nv_bfloat16* bp16l(int id) {
    switch (id) { case 1: return g_xnl; case 3: return g_kvnl; default: return g_hl; }
}

// ---------------- inline packed-tile scheduling ------------------------------
__device__ __forceinline__ int tile_row(int zi, int j, int* e_out) {
    int base = 0;
    for (int e = 0; e < 4; e++) {
        int nb = 0;
        #pragma unroll
        for (int b = 0; b < 8; b++) nb += (g_gates[b * 4 + e] != 0.f);
        int rows_e = nb * 144;
        int tiles_e = (rows_e + 63) >> 6;
        if (zi < base + tiles_e) {
            *e_out = e;
            int lrow = (zi - base) * 64 + j;
            if (lrow >= rows_e) return -1;
            int bi = lrow / 144, rr = lrow % 144;
            int b = 0, cnt = 0;
            for (; b < 8; b++) {
                if (g_gates[b * 4 + e] != 0.f) { if (cnt == bi) break; cnt++; }
            }
            int s, r0;
            if (rr < 64)       { s = 0; r0 = rr; }
            else if (rr < 112) { s = 1; r0 = rr - 64; }
            else               { s = 2; r0 = rr - 112; }
            return (e * 24 + b * 3 + s) * 64 + r0;
        }
        base += tiles_e;
    }
    return -2;
}

// ---------------- weight splitting (single launch) ---------------------------
__global__ void split_all(const float* __restrict__ w_attnin,
                          const float* __restrict__ w_attnout,
                          const float* __restrict__ w_fc,
                          const float* __restrict__ w_proj,
                          const float* __restrict__ w_outp) {
    long i = (long)blockIdx.x * blockDim.x + threadIdx.x;
    long stride = (long)gridDim.x * blockDim.x;
    for (; i < W_TOTAL; i += stride) {
        const float* src; long rel;
        if (i < OFF_ATTNOUT)      { src = w_attnin;  rel = i; }
        else if (i < OFF_FC)      { src = w_attnout; rel = i - OFF_ATTNOUT; }
        else if (i < OFF_PROJ)    { src = w_fc;      rel = i - OFF_FC; }
        else if (i < OFF_OUTP)    { src = w_proj;    rel = i - OFF_PROJ; }
        else                      { src = w_outp;    rel = i - OFF_OUTP; }
        float x = src[rel];
        __nv_bfloat16 h = __float2bfloat16(x);
        g_wh[i] = h;
        g_wl[i] = __float2bfloat16(x - __bfloat162float(h));
    }
}

// ---------------- block reductions -------------------------------------------
__device__ __forceinline__ float blockReduceSum(float v, float* sbuf) {
    int t = threadIdx.x;
    for (int o = 16; o; o >>= 1) v += __shfl_down_sync(0xffffffffu, v, o);
    if ((t & 31) == 0) sbuf[t >> 5] = v;
    __syncthreads();
    if (t < 8) {
        v = sbuf[t];
        for (int o = 4; o; o >>= 1) v += __shfl_down_sync(0xffu, v, o);
        if (t == 0) sbuf[0] = v;
    }
    __syncthreads();
    float r = sbuf[0];
    __syncthreads();
    return r;
}
__device__ __forceinline__ float blockReduceMax(float v, float* sbuf) {
    int t = threadIdx.x;
    for (int o = 16; o; o >>= 1) v = fmaxf(v, __shfl_down_sync(0xffffffffu, v, o));
    if ((t & 31) == 0) sbuf[t >> 5] = v;
    __syncthreads();
    if (t < 8) {
        v = sbuf[t];
        for (int o = 4; o; o >>= 1) v = fmaxf(v, __shfl_down_sync(0xffu, v, o));
        if (t == 0) sbuf[0] = v;
    }
    __syncthreads();
    float r = sbuf[0];
    __syncthreads();
    return r;
}

// ---------------- gating -----------------------------------------------------
__global__ void gate_kernel(const float* __restrict__ img,
                            const int* __restrict__ task_ids,
                            const int* __restrict__ elem_ids,
                            const float* __restrict__ task_emb,
                            const float* __restrict__ elem_emb,
                            const float* __restrict__ glw,
                            const float* __restrict__ glb,
                            const float* __restrict__ gw,
                            const float* __restrict__ gb) {
    int b = blockIdx.x;
    int t = threadIdx.x;
    __shared__ float gi[1536];
    __shared__ float sn[1536];
    __shared__ float red[32];
    __shared__ float lg[4];

    float acc0 = 0.f, acc1 = 0.f, acc2 = 0.f, acc3 = 0.f;
    const float* ib = img + (long)b * 576 * H_;
    for (int r = 0; r < 576; r++) {
        const float* row = ib + (long)r * H_;
        acc0 += row[t];        acc1 += row[t + 256];
        acc2 += row[t + 512];  acc3 += row[t + 768];
    }
    const float inv576 = 1.f / 576.f;
    gi[t]       = acc0 * inv576;  gi[t + 256] = acc1 * inv576;
    gi[t + 512] = acc2 * inv576;  gi[t + 768] = acc3 * inv576;
    gi[1024 + t] = task_emb[task_ids[b] * 256 + t];
    gi[1280 + t] = elem_emb[elem_ids[b] * 256 + t];
    __syncthreads();

    float s1 = 0.f;
    for (int d = t; d < 1536; d += 256) s1 += gi[d];
    s1 = blockReduceSum(s1, red);
    float m = s1 / 1536.f;
    float s2 = 0.f;
    for (int d = t; d < 1536; d += 256) { float dd = gi[d] - m; s2 += dd * dd; }
    s2 = blockReduceSum(s2, red);
    float rs = rsqrtf(s2 / 1536.f + 1e-5f);
    for (int d = t; d < 1536; d += 256) sn[d] = (gi[d] - m) * rs * glw[d] + glb[d];
    __syncthreads();

    for (int e = 0; e < 4; e++) {
        float pd = 0.f;
        for (int d = t; d < 1536; d += 256) pd += sn[d] * gw[e * 1536 + d];
        pd = blockReduceSum(pd, red);
        if (t == 0) {
            float l = pd + gb[e];
            lg[e] = fminf(fmaxf(l, -15.f), 15.f);
        }
        __syncthreads();
    }
    if (t == 0) {
        float mx = fmaxf(fmaxf(lg[0], lg[1]), fmaxf(lg[2], lg[3]));
        float pe[4]; float den = 0.f;
        for (int e = 0; e < 4; e++) { pe[e] = expf(lg[e] - mx); den += pe[e]; }
        for (int e = 0; e < 4; e++) pe[e] /= den;
        int i1 = 0;
        for (int e = 1; e < 4; e++) if (pe[e] > pe[i1]) i1 = e;
        int i2 = -1;
        for (int e = 0; e < 4; e++) {
            if (e == i1) continue;
            if (i2 < 0 || pe[e] > pe[i2]) i2 = e;
        }
        float sum2 = pe[i1] + pe[i2] + 1e-9f;
        for (int e = 0; e < 4; e++) g_gates[b * 4 + e] = 0.f;
        g_gates[b * 4 + i1] = pe[i1] / sum2;
        g_gates[b * 4 + i2] = pe[i2] / sum2;
    }
}

// ---------------- fused prep: build kv0/x + layer-0 LN (kv + x) --------------
__global__ void prep_kernel(const float* __restrict__ query,
                            const float* __restrict__ img,
                            const float* __restrict__ pp,
                            const float* __restrict__ ln1_w,
                            const float* __restrict__ ln1_b,
                            const float* __restrict__ ln1kv_w,
                            const float* __restrict__ ln1kv_b) {
    int p = blockIdx.y;
    int e = p / 24, r = p % 24, b = r / 3, s = r % 3;
    if (g_gates[b * 4 + e] == 0.f) return;
    int tk = blockIdx.x;
    int L = c_L[s];
    if (tk >= L) return;
    int sq = c_SQ[s];
    const float* src;
    if (tk < sq) {
        src = query + ((long)e * NQ_ + c_QO[s] + tk) * H_;
    } else {
        int j = c_IO[s] + tk - sq;
        src = (j < 576) ? img + ((long)b * 576 + j) * H_
                        : pp  + ((long)b * 192 + (j - 576)) * H_;
    }
    __shared__ float sx[1024];
    __shared__ float red[32];
    int t = threadIdx.x;
    float s1 = 0.f;
    #pragma unroll
    for (int j = 0; j < 4; j++) { float v = src[t + j * 256]; sx[t + j * 256] = v; s1 += v; }

    float* dst = g_kv0 + (long)p * 320 * H_ + (long)tk * H_;
    #pragma unroll
    for (int j = 0; j < 4; j++) dst[t + j * 256] = sx[t + j * 256];
    if (tk < sq) {
        float* xd = g_x + (long)p * 64 * H_ + (long)tk * H_;
        #pragma unroll
        for (int j = 0; j < 4; j++) xd[t + j * 256] = sx[t + j * 256];
    }

    s1 = blockReduceSum(s1, red);
    float m = s1 / 1024.f;
    float s2 = 0.f;
    #pragma unroll
    for (int j = 0; j < 4; j++) { float d = sx[t + j * 256] - m; s2 += d * d; }
    s2 = blockReduceSum(s2, red);
    float rs = rsqrtf(s2 / 1024.f + 1e-5f);

    const float* wkv = ln1kv_w + (long)(e * 2) * H_;
    const float* bkv = ln1kv_b + (long)(e * 2) * H_;
    long koff = (long)p * 320 * H_ + (long)tk * H_;
    #pragma unroll
    for (int j = 0; j < 4; j++) {
        int d = t + j * 256;
        float val = (sx[d] - m) * rs * wkv[d] + bkv[d];
        __nv_bfloat16 h = __float2bfloat16(val);
        g_kvnh[koff + d] = h;
        g_kvnl[koff + d] = __float2bfloat16(val - __bfloat162float(h));
    }
    if (tk < sq) {
        const float* wq = ln1_w + (long)(e * 2) * H_;
        const float* bq = ln1_b + (long)(e * 2) * H_;
        long xoff = (long)p * 64 * H_ + (long)tk * H_;
        #pragma unroll
        for (int j = 0; j < 4; j++) {
            int d = t + j * 256;
            float val = (sx[d] - m) * rs * wq[d] + bq[d];
            __nv_bfloat16 h = __float2bfloat16(val);
            g_xnh[xoff + d] = h;
            g_xnl[xoff + d] = __float2bfloat16(val - __bfloat162float(h));
        }
    }
}

// ---------------- row LayerNorm → bf16 hi/lo ---------------------------------
__global__ void ln_rows(int src, int dst,
                        const float* __restrict__ wbase,
                        const float* __restrict__ bbase,
                        int m_is_L, int layer) {
    int p = blockIdx.y;
    int e = p / 24, r = p % 24, b = r / 3, s = r % 3;
    if (g_gates[b * 4 + e] == 0.f) return;
    int M = m_is_L ? c_L[s] : c_SQ[s];
    int row = blockIdx.x;
    if (row >= M) return;
    const float* x = bufptr(src) + (long)p * bufstride(src) + (long)row * H_;
    long doff = (long)p * bufstride(dst) + (long)row * H_;
    __nv_bfloat16* yh = bp16h(dst) + doff;
    __nv_bfloat16* yl = bp16l(dst) + doff;
    const float* w  = wbase + (long)(e * 2 + layer) * H_;
    const float* bb = bbase + (long)(e * 2 + layer) * H_;
    __shared__ float sx[1024];
    __shared__ float red[32];
    int t = threadIdx.x;
    float s1 = 0.f;
    #pragma unroll
    for (int j = 0; j < 4; j++) { float v = x[t + j * 256]; sx[t + j * 256] = v; s1 += v; }
    s1 = blockReduceSum(s1, red);
    float m = s1 / 1024.f;
    float s2 = 0.f;
    #pragma unroll
    for (int j = 0; j < 4; j++) { float d = sx[t + j * 256] - m; s2 += d * d; }
    s2 = blockReduceSum(s2, red);
    float rs = rsqrtf(s2 / 1024.f + 1e-5f);
    #pragma unroll
    for (int j = 0; j < 4; j++) {
        int d = t + j * 256;
        float val = (sx[d] - m) * rs * w[d] + bb[d];
        __nv_bfloat16 h = __float2bfloat16(val);
        yh[d] = h;
        yl[d] = __float2bfloat16(val - __bfloat162float(h));
    }
}

// ---------------- tensor-core GEMM: BM=64 BN=128, cp.async, 2-stage ----------
#define SPITCH 40
#define STG_BYTES 30720
#define TSM_TOTAL (2 * STG_BYTES)

struct GArgs {
    int a_id; int c_id;
    long wh_off; long w_stride;
    const float* bias; long bias_stride;
    const float* ls;
    int N; int K;
    int m_is_L;
    int epi;     // 0 fp32 store, 1 gelu->bf16hi/lo, 2 C += ls*(c+bias), 4 kv-split
    int layer;
    int packed;
};

__device__ __forceinline__ void mma_bf16(float* d, const uint32_t* a, const uint32_t* b) {
    asm volatile(
        "mma.sync.aligned.m16n8k16.row.col.f32.bf16.bf16.f32 "
        "{%0,%1,%2,%3}, {%4,%5,%6,%7}, {%8,%9}, {%0,%1,%2,%3};\n"
        : "+f"(d[0]), "+f"(d[1]), "+f"(d[2]), "+f"(d[3])
        : "r"(a[0]), "r"(a[1]), "r"(a[2]), "r"(a[3]), "r"(b[0]), "r"(b[1]));
}
__device__ __forceinline__ void ldsm4(uint32_t& r0, uint32_t& r1, uint32_t& r2, uint32_t& r3,
                                      uint32_t addr) {
    asm volatile("ldmatrix.sync.aligned.m8n8.x4.shared.b16 {%0,%1,%2,%3}, [%4];"
                 : "=r"(r0), "=r"(r1), "=r"(r2), "=r"(r3) : "r"(addr));
}
__device__ __forceinline__ void split8(float4 f0, float4 f1, uint4& hi, uint4& lo) {
    __nv_bfloat162 h0 = __floats2bfloat162_rn(f0.x, f0.y);
    __nv_bfloat162 h1 = __floats2bfloat162_rn(f0.z, f0.w);
    __nv_bfloat162 h2 = __floats2bfloat162_rn(f1.x, f1.y);
    __nv_bfloat162 h3 = __floats2bfloat162_rn(f1.z, f1.w);
    float2 a0 = __bfloat1622float2(h0), a1 = __bfloat1622float2(h1);
    float2 a2 = __bfloat1622float2(h2), a3 = __bfloat1622float2(h3);
    __nv_bfloat162 l0 = __floats2bfloat162_rn(f0.x - a0.x, f0.y - a0.y);
    __nv_bfloat162 l1 = __floats2bfloat162_rn(f0.z - a1.x, f0.w - a1.y);
    __nv_bfloat162 l2 = __floats2bfloat162_rn(f1.x - a2.x, f1.y - a2.y);
    __nv_bfloat162 l3 = __floats2bfloat162_rn(f1.z - a3.x, f1.w - a3.y);
    hi.x = *(uint32_t*)&h0; hi.y = *(uint32_t*)&h1; hi.z = *(uint32_t*)&h2; hi.w = *(uint32_t*)&h3;
    lo.x = *(uint32_t*)&l0; lo.y = *(uint32_t*)&l1; lo.z = *(uint32_t*)&l2; lo.w = *(uint32_t*)&l3;
}

__device__ __forceinline__ void cpa16(uint32_t dst, const void* src) {
    asm volatile("cp.async.cg.shared.global [%0], [%1], 16;" :: "r"(dst), "l"(src));
}
__device__ __forceinline__ void cpa16z(uint32_t dst) {
    asm volatile("cp.async.cg.shared.global [%0], [%1], 16, 0;"
                 :: "r"(dst), "l"((const void*)g_wh));
}
#define CP_COMMIT asm volatile("cp.async.commit_group;" ::: "memory")
#define CP_WAIT1  asm volatile("cp.async.wait_group 1;" ::: "memory")
#define CP_WAIT0  asm volatile("cp.async.wait_group 0;" ::: "memory")

__global__ void __launch_bounds__(256, 3) gemm_k(GArgs g) {
    int zi = blockIdx.z;
    int e = 0, p = 0, M = 64, m0 = 0;
    long pbaseA = 0;

    if (g.packed) {
        int probe = tile_row(zi, 0, &e);
        if (probe == -2) return;
    } else {
        p = zi;
        e = p / 24;
        int r = p % 24, b = r / 3, s = r % 3;
        if (g_gates[b * 4 + e] == 0.f) return;
        M = g.m_is_L ? c_L[s] : c_SQ[s];
        m0 = blockIdx.x * 64;
        if (m0 >= M) return;
        pbaseA = (long)p * bufstride(g.a_id);
    }
    int n0 = blockIdx.y * 128;

    const __nv_bfloat16* Wh = g_wh + g.wh_off + (long)(e * 2 + g.layer) * g.w_stride;
    const __nv_bfloat16* Wl = g_wl + g.wh_off + (long)(e * 2 + g.layer) * g.w_stride;
    const float* bias = g.bias + (long)(e * 2 + g.layer) * g.bias_stride;

    extern __shared__ char dsm[];
    uint32_t smem_u = (uint32_t)__cvta_generic_to_shared(dsm);

    int tid = threadIdx.x;
    // A loader: row = tid>>2 (64 rows), 16B chunk = (tid&3)*8 elems
    int arow = tid >> 2, akq = (tid & 3) << 3;
    const __nv_bfloat16* ahrow = nullptr;
    const __nv_bfloat16* alrow = nullptr;
    if (g.packed) {
        int e2;
        int rm = tile_row(zi, arow, &e2);
        if (rm >= 0) {
            long aoff = (long)rm * g.K + akq;
            ahrow = bp16h(g.a_id) + aoff;
            alrow = bp16l(g.a_id) + aoff;
        }
    } else if (m0 + arow < M) {
        long aoff = pbaseA + (long)(m0 + arow) * g.K + akq;
        ahrow = bp16h(g.a_id) + aoff;
        alrow = bp16l(g.a_id) + aoff;
    }
    // W loader: row = tid>>1 (128 rows), 32B = two 16B chunks at (tid&1)*16
    int wrow = tid >> 1, wkq = (tid & 1) << 4;
    const __nv_bfloat16* whp = Wh + (long)(n0 + wrow) * g.K + wkq;
    const __nv_bfloat16* wlp = Wl + (long)(n0 + wrow) * g.K + wkq;

    uint32_t sA_off = (uint32_t)(arow * SPITCH + akq) * 2;
    uint32_t sW_off = (uint32_t)(wrow * SPITCH + wkq) * 2;

    // compute mapping: 8 warps (2 x 4), warp tile 32x32
    int lane = tid & 31, w = tid >> 5;
    int gq_ = lane >> 2, qq = lane & 3;
    int wm = w & 1, wn = w >> 1;
    int abase = wm * 32, wbase = wn * 32;

    int lr = lane & 7, tq = lane >> 3;
    int a_r = abase + ((tq & 1) << 3) + lr;
    int a_k = (tq >> 1) << 3;
    int b_r = wbase + ((tq >> 1) << 3) + lr;
    int b_k = (tq & 1) << 3;

    float acc[2][4][4];
    #pragma unroll
    for (int i = 0; i < 2; i++)
        #pragma unroll
        for (int j = 0; j < 4; j++)
            #pragma unroll
            for (int k = 0; k < 4; k++) acc[i][j][k] = 0.f;

    int nc = g.K >> 5;

    auto prefetch = [&](int c, int st) {
        uint32_t sb = smem_u + st * STG_BYTES;
        long ko = (long)c << 5;
        if (ahrow) {
            cpa16(sb + sA_off, ahrow + ko);
            cpa16(sb + 5120 + sA_off, alrow + ko);
        } else {
            cpa16z(sb + sA_off);
            cpa16z(sb + 5120 + sA_off);
        }
        uint32_t wb = sb + 10240 + sW_off;
        cpa16(wb,          whp + ko);
        cpa16(wb + 16,     whp + ko + 8);
        cpa16(wb + 10240,      wlp + ko);
        cpa16(wb + 10240 + 16, wlp + ko + 8);
        CP_COMMIT;
    };

    prefetch(0, 0);
    if (nc > 1) prefetch(1, 1);

    for (int c = 0; c < nc; c++) {
        int st = c & 1;
        if (c == nc - 1) { CP_WAIT0; } else { CP_WAIT1; }
        __syncthreads();

        uint32_t aH = smem_u + st * STG_BYTES;
        uint32_t aL = aH + 5120;
        uint32_t wH = aH + 10240;
        uint32_t wL = aH + 20480;

        #pragma unroll
        for (int ks = 0; ks < 32; ks += 16) {
            uint32_t Ah[2][4], Al[2][4], Bh[4][2], Bl[4][2];
            #pragma unroll
            for (int mf = 0; mf < 2; mf++) {
                uint32_t off = ((a_r + mf * 16) * SPITCH + a_k + ks) * 2;
                ldsm4(Ah[mf][0], Ah[mf][1], Ah[mf][2], Ah[mf][3], aH + off);
                ldsm4(Al[mf][0], Al[mf][1], Al[mf][2], Al[mf][3], aL + off);
            }
            #pragma unroll
            for (int nfp = 0; nfp < 2; nfp++) {
                uint32_t off = ((b_r + nfp * 16) * SPITCH + b_k + ks) * 2;
                ldsm4(Bh[nfp*2][0], Bh[nfp*2][1], Bh[nfp*2+1][0], Bh[nfp*2+1][1], wH + off);
                ldsm4(Bl[nfp*2][0], Bl[nfp*2][1], Bl[nfp*2+1][0], Bl[nfp*2+1][1], wL + off);
            }
            #pragma unroll
            for (int mf = 0; mf < 2; mf++)
                #pragma unroll
                for (int nf = 0; nf < 4; nf++) {
                    mma_bf16(acc[mf][nf], Ah[mf], Bh[nf]);
                    mma_bf16(acc[mf][nf], Ah[mf], Bl[nf]);
                    mma_bf16(acc[mf][nf], Al[mf], Bh[nf]);
                }
        }
        __syncthreads();
        if (c + 2 < nc) prefetch(c + 2, st);
    }

    // epilogue
    float* C = bufptr(g.c_id);
    __nv_bfloat16* Ch = bp16h(g.c_id);
    __nv_bfloat16* Cl = bp16l(g.c_id);
    long pbaseC = g.packed ? 0 : (long)p * bufstride(g.c_id);
    long pbaseKV = (long)p * 320L * H_;
    const float* lsp = (g.epi == 2) ? (g.ls + (long)(e * 2 + g.layer) * H_) : nullptr;

    #pragma unroll
    for (int mf = 0; mf < 2; mf++) {
        #pragma unroll
        for (int half = 0; half < 2; half++) {
            int ml = abase + mf * 16 + gq_ + half * 8;
            long rowoff;
            if (g.packed) {
                int e2;
                int rm = tile_row(zi, ml, &e2);
                if (rm < 0) continue;
                rowoff = (long)rm * g.N;
            } else {
                int m = m0 + ml;
                if (m >= M) continue;
                rowoff = pbaseC + (long)m * g.N;
                if (g.epi == 4) rowoff = pbaseKV + (long)m * (long)H_;
            }
            #pragma unroll
            for (int nf = 0; nf < 4; nf++) {
                int n = n0 + wbase + nf * 8 + qq * 2;
                float v0 = acc[mf][nf][half * 2 + 0] + bias[n];
                float v1 = acc[mf][nf][half * 2 + 1] + bias[n + 1];
                if (g.epi == 0) {
                    long idx = rowoff + n;
                    C[idx] = v0; C[idx + 1] = v1;
                } else if (g.epi == 1) {
                    long idx = rowoff + n;
                    float t0 = v0 * 0.5f * (1.f + erff(v0 * 0.70710678118654752f));
                    float t1 = v1 * 0.5f * (1.f + erff(v1 * 0.70710678118654752f));
                    __nv_bfloat16 h0 = __float2bfloat16(t0);
                    __nv_bfloat16 h1 = __float2bfloat16(t1);
                    Ch[idx] = h0;     Ch[idx + 1] = h1;
                    Cl[idx]     = __float2bfloat16(t0 - __bfloat162float(h0));
                    Cl[idx + 1] = __float2bfloat16(t1 - __bfloat162float(h1));
                } else if (g.epi == 2) {
                    long idx = rowoff + n;
                    C[idx]     += lsp[n] * v0;
                    C[idx + 1] += lsp[n + 1] * v1;
                } else {
                    float* dst = (n < 1024) ? g_k : g_v;
                    long idx = rowoff + (n & 1023);
                    dst[idx] = v0; dst[idx + 1] = v1;
                }
            }
        }
    }
}

// ---------------- attention: 4 q-rows per block ------------------------------
__global__ void attn_kernel() {
    int p = blockIdx.z;
    int e = p / 24, r = p % 24, b = r / 3, s = r % 3;
    if (g_gates[b * 4 + e] == 0.f) return;
    int sq = c_SQ[s];
    int r0 = blockIdx.x * 4;
    if (r0 >= sq) return;
    int L = c_L[s];
    int h = blockIdx.y;
    int t = threadIdx.x;

    __shared__ float sc[4][320];
    __shared__ float qv[4][64];
    __shared__ float red[32];
    __shared__ float cbuf[4][4][64];
    __shared__ float inv[4];

    const float* Qb = g_q + (long)p * 64 * H_ + (long)r0 * H_ + h * 64;
    const float* K  = g_k + (long)p * 320 * H_ + h * 64;
    const float* V  = g_v + (long)p * 320 * H_ + h * 64;

    qv[t >> 6][t & 63] = Qb[(long)(t >> 6) * H_ + (t & 63)];
    __syncthreads();

    for (int k = t; k < L; k += 256) {
        const float* kr = K + (long)k * H_;
        float d0 = 0.f, d1 = 0.f, d2 = 0.f, d3 = 0.f;
        #pragma unroll
        for (int dd = 0; dd < 64; dd++) {
            float kvv = kr[dd];
            d0 += qv[0][dd] * kvv;
            d1 += qv[1][dd] * kvv;
            d2 += qv[2][dd] * kvv;
            d3 += qv[3][dd] * kvv;
        }
        sc[0][k] = d0 * 0.125f;
        sc[1][k] = d1 * 0.125f;
        sc[2][k] = d2 * 0.125f;
        sc[3][k] = d3 * 0.125f;
    }
    __syncthreads();

    for (int rr = 0; rr < 4; rr++) {
        float mx = -1e30f;
        for (int k = t; k < L; k += 256) mx = fmaxf(mx, sc[rr][k]);
        mx = blockReduceMax(mx, red);
        float sum = 0.f;
        for (int k = t; k < L; k += 256) {
            float ev = expf(sc[rr][k] - mx);
            sc[rr][k] = ev;
            sum += ev;
        }
        sum = blockReduceSum(sum, red);
        if (t == 0) inv[rr] = 1.f / sum;
        __syncthreads();
    }

    int d = t & 63, ch = t >> 6;
    float a0 = 0.f, a1 = 0.f, a2 = 0.f, a3 = 0.f;
    for (int k = ch; k < L; k += 4) {
        float vv = V[(long)k * H_ + d];
        a0 += sc[0][k] * vv;
        a1 += sc[1][k] * vv;
        a2 += sc[2][k] * vv;
        a3 += sc[3][k] * vv;
    }
    cbuf[ch][0][d] = a0;
    cbuf[ch][1][d] = a1;
    cbuf[ch][2][d] = a2;
    cbuf[ch][3][d] = a3;
    __syncthreads();

    {
        int rr = t >> 6, dd = t & 63;
        float o = (cbuf[0][rr][dd] + cbuf[1][rr][dd] + cbuf[2][rr][dd] + cbuf[3][rr][dd]) * inv[rr];
        long ooff = (long)p * 64 * H_ + (long)(r0 + rr) * H_ + h * 64 + dd;
        __nv_bfloat16 oh = __float2bfloat16(o);
        g_xnh[ooff] = oh;
        g_xnl[ooff] = __float2bfloat16(o - __bfloat162float(oh));
    }
}

// ---------------- expert-weighted output projection (legacy path) ------------
__global__ void __launch_bounds__(256) out_gemm(const float* __restrict__ outp_b) {
    int b = blockIdx.z;
    int m0 = blockIdx.x * 64;
    int n0 = blockIdx.y * 128;

    extern __shared__ char dsm[];
    uint32_t smem_u = (uint32_t)__cvta_generic_to_shared(dsm);

    int tid = threadIdx.x;
    int arow = tid >> 2, akq = (tid & 3) << 3;
    int wrow = tid >> 1, wkq = (tid & 1) << 4;
    int lane = tid & 31, w = tid >> 5;
    int gq_ = lane >> 2, qq = lane & 3;
    int wm = w & 1, wn = w >> 1;
    int abase = wm * 32, wbase = wn * 32;

    int lr = lane & 7, tq = lane >> 3;
    int a_r = abase + ((tq & 1) << 3) + lr;
    int a_k = (tq >> 1) << 3;
    int b_r = wbase + ((tq >> 1) << 3) + lr;
    int b_k = (tq & 1) << 3;

    int qg = m0 + arow;
    bool aval = qg < NQ_;
    int s = 0, lrq = 0;
    if (aval) {
        s = (qg < 64) ? 0 : ((qg < 112) ? 1 : 2);
        lrq = qg - c_QO[s];
    }

    float tot[2][4][4];
    #pragma unroll
    for (int i = 0; i < 2; i++)
        #pragma unroll
        for (int j = 0; j < 4; j++)
            #pragma unroll
            for (int k = 0; k < 4; k++) tot[i][j][k] = 0.f;

    for (int e = 0; e < 4; e++) {
        float gt = g_gates[b * 4 + e];
        if (gt == 0.f) continue;
        const float* aptr = g_x + ((long)(e * 24 + b * 3 + s) * 64 + lrq) * H_ + akq;
        long wb = OFF_OUTP + (long)e * OUT_ * H_ + (long)(n0 + wrow) * H_ + wkq;
        const __nv_bfloat16* whp = g_wh + wb;
        const __nv_bfloat16* wlp = g_wl + wb;

        float acc[2][4][4];
        #pragma unroll
        for (int i = 0; i < 2; i++)
            #pragma unroll
            for (int j = 0; j < 4; j++)
                #pragma unroll
                for (int k = 0; k < 4; k++) acc[i][j][k] = 0.f;

        float4 f0, f1;
        uint4 rah, ral, vh0, vh1, vl0, vl1;
        uint4 zz = make_uint4(0u, 0u, 0u, 0u);

        f0 = f1 = make_float4(0.f, 0.f, 0.f, 0.f);
        if (aval) { f0 = *(const float4*)(aptr); f1 = *(const float4*)(aptr + 4); }
        split8(f0, f1, rah, ral);
        if (!aval) { rah = zz; ral = zz; }
        vh0 = *(const uint4*)(whp);  vh1 = *(const uint4*)(whp + 8);
        vl0 = *(const uint4*)(wlp);  vl1 = *(const uint4*)(wlp + 8);

        __syncthreads();
        {
            __nv_bfloat16* sAh = (__nv_bfloat16*)(dsm);
            __nv_bfloat16* sAl = (__nv_bfloat16*)(dsm + 5120);
            __nv_bfloat16* sWh = (__nv_bfloat16*)(dsm + 10240);
            __nv_bfloat16* sWl = (__nv_bfloat16*)(dsm + 20480);
            *(uint4*)&sAh[arow * SPITCH + akq] = rah;
            *(uint4*)&sAl[arow * SPITCH + akq] = ral;
            *(uint4*)&sWh[wrow * SPITCH + wkq]     = vh0;
            *(uint4*)&sWh[wrow * SPITCH + wkq + 8] = vh1;
            *(uint4*)&sWl[wrow * SPITCH + wkq]     = vl0;
            *(uint4*)&sWl[wrow * SPITCH + wkq + 8] = vl1;
        }
        __syncthreads();

        const int nc = H_ >> 5;
        for (int c = 0; c < nc; c++) {
            int st = c & 1;
            bool nx = (c + 1 < nc);
            if (nx) {
                long off = (long)(c + 1) << 5;
                f0 = f1 = make_float4(0.f, 0.f, 0.f, 0.f);
                if (aval) { f0 = *(const float4*)(aptr + off); f1 = *(const float4*)(aptr + off + 4); }
                split8(f0, f1, rah, ral);
                if (!aval) { rah = zz; ral = zz; }
                vh0 = *(const uint4*)(whp + off);  vh1 = *(const uint4*)(whp + off + 8);
                vl0 = *(const uint4*)(wlp + off);  vl1 = *(const uint4*)(wlp + off + 8);
            }

            uint32_t aH = smem_u + st * STG_BYTES;
            uint32_t aL = aH + 5120;
            uint32_t wH = aH + 10240;
            uint32_t wL = aH + 20480;

            #pragma unroll
            for (int ks = 0; ks < 32; ks += 16) {
                uint32_t Ah[2][4], Al[2][4], Bh[4][2], Bl[4][2];
                #pragma unroll
                for (int mf = 0; mf < 2; mf++) {
                    uint32_t off = ((a_r + mf * 16) * SPITCH + a_k + ks) * 2;
                    ldsm4(Ah[mf][0], Ah[mf][1], Ah[mf][2], Ah[mf][3], aH + off);
                    ldsm4(Al[mf][0], Al[mf][1], Al[mf][2], Al[mf][3], aL + off);
                }
                #pragma unroll
                for (int nfp = 0; nfp < 2; nfp++) {
                    uint32_t off = ((b_r + nfp * 16) * SPITCH + b_k + ks) * 2;
                    ldsm4(Bh[nfp*2][0], Bh[nfp*2][1], Bh[nfp*2+1][0], Bh[nfp*2+1][1], wH + off);
                    ldsm4(Bl[nfp*2][0], Bl[nfp*2][1], Bl[nfp*2+1][0], Bl[nfp*2+1][1], wL + off);
                }
                #pragma unroll
                for (int mf = 0; mf < 2; mf++)
                    #pragma unroll
                    for (int nf = 0; nf < 4; nf++) {
                        mma_bf16(acc[mf][nf], Ah[mf], Bh[nf]);
                        mma_bf16(acc[mf][nf], Ah[mf], Bl[nf]);
                        mma_bf16(acc[mf][nf], Al[mf], Bh[nf]);
                    }
            }

            if (nx) {
                char* base = dsm + (st ^ 1) * STG_BYTES;
                __nv_bfloat16* sAh = (__nv_bfloat16*)(base);
                __nv_bfloat16* sAl = (__nv_bfloat16*)(base + 5120);
                __nv_bfloat16* sWh = (__nv_bfloat16*)(base + 10240);
                __nv_bfloat16* sWl = (__nv_bfloat16*)(base + 20480);
                *(uint4*)&sAh[arow * SPITCH + akq] = rah;
                *(uint4*)&sAl[arow * SPITCH + akq] = ral;
                *(uint4*)&sWh[wrow * SPITCH + wkq]     = vh0;
                *(uint4*)&sWh[wrow * SPITCH + wkq + 8] = vh1;
                *(uint4*)&sWl[wrow * SPITCH + wkq]     = vl0;
                *(uint4*)&sWl[wrow * SPITCH + wkq + 8] = vl1;
            }
            __syncthreads();
        }

        const float* bias = outp_b + (long)e * OUT_;
        #pragma unroll
        for (int mf = 0; mf < 2; mf++)
            #pragma unroll
            for (int nf = 0; nf < 4; nf++) {
                int n = n0 + wbase + nf * 8 + qq * 2;
                tot[mf][nf][0] += gt * (acc[mf][nf][0] + bias[n]);
                tot[mf][nf][1] += gt * (acc[mf][nf][1] + bias[n + 1]);
                tot[mf][nf][2] += gt * (acc[mf][nf][2] + bias[n]);
                tot[mf][nf][3] += gt * (acc[mf][nf][3] + bias[n + 1]);
            }
    }

    #pragma unroll
    for (int mf = 0; mf < 2; mf++) {
        #pragma unroll
        for (int half = 0; half < 2; half++) {
            int m = m0 + abase + mf * 16 + gq_ + half * 8;
            if (m >= NQ_) continue;
            #pragma unroll
            for (int nf = 0; nf < 4; nf++) {
                int n = n0 + wbase + nf * 8 + qq * 2;
                g_comb[((long)b * NQ_ + m) * OUT_ + n]     = tot[mf][nf][half * 2 + 0];
                g_comb[((long)b * NQ_ + m) * OUT_ + n + 1] = tot[mf][nf][half * 2 + 1];
            }
        }
    }
}

// ---------------- final RMS + scaling ----------------------------------------
__global__ void rms_kernel(const float* __restrict__ final_w,
                           const float* __restrict__ out_gain,
                           float* __restrict__ out) {
    int q = blockIdx.x, b = blockIdx.y;
    int t = threadIdx.x;
    const float* c = g_comb + ((long)b * NQ_ + q) * OUT_;
    float s2 = 0.f;
    for (int o = t; o < OUT_; o += 256) { float v = c[o]; s2 += v * v; }
    __shared__ float red[32];
    s2 = blockReduceSum(s2, red);
    float rs = rsqrtf(s2 / (float)OUT_ + 1e-6f);
    float* orow = out + ((long)b * NQ_ + q) * OUT_;
    for (int o = t; o < OUT_; o += 256) orow[o] = c[o] * rs * final_w[o] * out_gain[o];
}

// ---------------- host driver ------------------------------------------------
extern "C" void kernel_launch(void* const* d_in, const int* in_sizes, int n_in,
                              void* d_out, int out_size) {
    const float* image_embs = (const float*)d_in[0];
    const float* phys       = (const float*)d_in[1];
    const int*   task_ids   = (const int*)d_in[2];
    const int*   elem_ids   = (const int*)d_in[3];
    const float* query      = (const float*)d_in[4];
    const float* ln1_w      = (const float*)d_in[5];
    const float* ln1_b      = (const float*)d_in[6];
    const float* ln1kv_w    = (const float*)d_in[7];
    const float* ln1kv_b    = (const float*)d_in[8];
    const float* attn_in_w  = (const float*)d_in[9];
    const float* attn_in_b  = (const float*)d_in[10];
    const float* attn_out_w = (const float*)d_in[11];
    const float* attn_out_b = (const float*)d_in[12];
    const float* ls1        = (const float*)d_in[13];
    const float* ls2        = (const float*)d_in[14];
    const float* ln2_w      = (const float*)d_in[15];
    const float* ln2_b      = (const float*)d_in[16];
    const float* fc_w       = (const float*)d_in[17];
    const float* fc_b       = (const float*)d_in[18];
    const float* proj_w     = (const float*)d_in[19];
    const float* proj_b     = (const float*)d_in[20];
    const float* outp_w     = (const float*)d_in[21];
    const float* outp_b     = (const float*)d_in[22];
    const float* task_emb   = (const float*)d_in[23];
    const float* elem_emb   = (const float*)d_in[24];
    const float* gate_ln_w  = (const float*)d_in[25];
    const float* gate_ln_b  = (const float*)d_in[26];
    const float* gate_w     = (const float*)d_in[27];
    const float* gate_b     = (const float*)d_in[28];
    const float* output_gain= (const float*)d_in[29];
    const float* final_w    = (const float*)d_in[30];
    (void)in_sizes; (void)n_in; (void)out_size;

    cudaFuncSetAttribute(gemm_k,   cudaFuncAttributeMaxDynamicSharedMemorySize, TSM_TOTAL);
    cudaFuncSetAttribute(out_gemm, cudaFuncAttributeMaxDynamicSharedMemorySize, TSM_TOTAL);

    split_all<<<8192, 256>>>(attn_in_w, attn_out_w, fc_w, proj_w, outp_w);   // 1
    gate_kernel<<<B_, 256>>>(image_embs, task_ids, elem_ids, task_emb, elem_emb,
                             gate_ln_w, gate_ln_b, gate_w, gate_b);          // 2
    prep_kernel<<<dim3(320, NP_), 256>>>(query, image_embs, phys,
                                         ln1_w, ln1_b, ln1kv_w, ln1kv_b);    // 3

    for (int l = 0; l < 2; l++) {
        if (l == 1) ln_rows<<<dim3(64, NP_), 256>>>(0, 1, ln1_w, ln1_b, 0, 1);

        GArgs gq = {};
        gq.a_id = 1; gq.c_id = 4;
        gq.wh_off = OFF_ATTNIN; gq.w_stride = 3072L * 1024;
        gq.bias = attn_in_b; gq.bias_stride = 3072;
        gq.ls = nullptr; gq.N = 1024; gq.K = 1024;
        gq.m_is_L = 0; gq.epi = 0; gq.layer = l; gq.packed = 1;
        gemm_k<<<dim3(1, 8, MAXT), 256, TSM_TOTAL>>>(gq);                    // 4 (l=0, profiled)

        if (l == 1) ln_rows<<<dim3(320, NP_), 256>>>(2, 3, ln1kv_w, ln1kv_b, 1, 1);

        GArgs gkv = {};
        gkv.a_id = 3; gkv.c_id = 5;
        gkv.wh_off = OFF_ATTNIN + 1024L * 1024; gkv.w_stride = 3072L * 1024;
        gkv.bias = attn_in_b + 1024; gkv.bias_stride = 3072;
        gkv.ls = nullptr; gkv.N = 2048; gkv.K = 1024;
        gkv.m_is_L = 1; gkv.epi = 4; gkv.layer = l; gkv.packed = 0;
        gemm_k<<<dim3(5, 16, NP_), 256, TSM_TOTAL>>>(gkv);

        attn_kernel<<<dim3(16, 16, NP_), 256>>>();

        GArgs go = {};
        go.a_id = 1; go.c_id = 0;
        go.wh_off = OFF_ATTNOUT; go.w_stride = 1024L * 1024;
        go.bias = attn_out_b; go.bias_stride = 1024;
        go.ls = ls1; go.N = 1024; go.K = 1024;
        go.m_is_L = 0; go.epi = 2; go.layer = l; go.packed = 1;
        gemm_k<<<dim3(1, 8, MAXT), 256, TSM_TOTAL>>>(go);

        ln_rows<<<dim3(64, NP_), 256>>>(0, 1, ln2_w, ln2_b, 0, l);

        GArgs gf = {};
        gf.a_id = 1; gf.c_id = 7;
        gf.wh_off = OFF_FC; gf.w_stride = 4096L * 1024;
        gf.bias = fc_b; gf.bias_stride = 4096;
        gf.ls = nullptr; gf.N = 4096; gf.K = 1024;
        gf.m_is_L = 0; gf.epi = 1; gf.layer = l; gf.packed = 1;
        gemm_k<<<dim3(1, 32, MAXT), 256, TSM_TOTAL>>>(gf);

        GArgs gp = {};
        gp.a_id = 7; gp.c_id = 0;
        gp.wh_off = OFF_PROJ; gp.w_stride = 1024L * 4096;
        gp.bias = proj_b; gp.bias_stride = 1024;
        gp.ls = ls2; gp.N = 1024; gp.K = 4096;
        gp.m_is_L = 0; gp.epi = 2; gp.layer = l; gp.packed = 1;
        gemm_k<<<dim3(1, 8, MAXT), 256, TSM_TOTAL>>>(gp);
    }

    out_gemm<<<dim3(3, 32, B_), 256, TSM_TOTAL>>>(outp_b);
    rms_kernel<<<dim3(NQ_, B_), 256>>>(final_w, output_gain, (float*)d_out);
}